// round 11
// baseline (speedup 1.0000x reference)
#include <cuda_runtime.h>
#include <math.h>

#define NN 1024
#define NT 256
#define BB 32

typedef unsigned long long u64;

// ---------------- device scratch ----------------
__device__ float2   g_pa[BB * NN];
__device__ float2   g_pam[BB * NN];
__device__ float2   g_tw[1024];           // W_1024^k, full table
__device__ double   g_accS[BB], g_accST[BB], g_accT[BB], g_accT2[BB];
__device__ unsigned g_accMax[BB];
__device__ float    g_mse[BB];

__device__ __forceinline__ float2 cmulf(float2 a, float2 b) {
    return make_float2(a.x * b.x - a.y * b.y, a.x * b.y + a.y * b.x);
}
__device__ __forceinline__ float2 cadd(float2 a, float2 b) { return make_float2(a.x + b.x, a.y + b.y); }
__device__ __forceinline__ float2 csub(float2 a, float2 b) { return make_float2(a.x - b.x, a.y - b.y); }

// ---------------- packed helpers (one complex value per u64) ----------------
__device__ __forceinline__ u64 F2U(float2 v) {
    u64 r; asm("mov.b64 %0,{%1,%2};" : "=l"(r) : "f"(v.x), "f"(v.y)); return r;
}
__device__ __forceinline__ float2 U2F(u64 v) {
    float2 r; asm("mov.b64 {%0,%1},%2;" : "=f"(r.x), "=f"(r.y) : "l"(v)); return r;
}
__device__ __forceinline__ u64 PADD(u64 a, u64 b) {
    u64 r; asm("add.rn.f32x2 %0,%1,%2;" : "=l"(r) : "l"(a), "l"(b)); return r;
}
__device__ __forceinline__ u64 PSUB(u64 a, u64 b) {
    const u64 n1 = 0xBF800000BF800000ULL;
    u64 r; asm("fma.rn.f32x2 %0,%1,%2,%3;" : "=l"(r) : "l"(b), "l"(n1), "l"(a)); return r;
}

// radix-4 DIF butterfly: packed adds, scalar cross-terms + cmuls
#define BFLY4P(A, Bq, C, D, W1, W2, W3) do {                                  \
    u64 ua = F2U(A), ub = F2U(Bq), uc = F2U(C), ud = F2U(D);                  \
    u64 t0 = PADD(ua, uc), t1 = PSUB(ua, uc);                                 \
    u64 t2 = PADD(ub, ud), t3 = PSUB(ub, ud);                                 \
    A = U2F(PADD(t0, t2));                                                    \
    float2 ci = U2F(PSUB(t0, t2));                                            \
    float2 f1 = U2F(t1), f3 = U2F(t3);                                        \
    float bx = f1.x + f3.y, by = f1.y - f3.x;                                 \
    float dx = f1.x - f3.y, dy = f1.y + f3.x;                                 \
    Bq = make_float2(bx * W1.x - by * W1.y, bx * W1.y + by * W1.x);           \
    C  = make_float2(ci.x * W2.x - ci.y * W2.y, ci.x * W2.y + ci.y * W2.x);   \
    D  = make_float2(dx * W3.x - dy * W3.y, dx * W3.y + dy * W3.x);           \
} while (0)

// identity-twiddle butterfly (W1=W2=W3=1): pure adds
#define BFLY4P0(A, Bq, C, D) do {                                             \
    u64 ua = F2U(A), ub = F2U(Bq), uc = F2U(C), ud = F2U(D);                  \
    u64 t0 = PADD(ua, uc), t1 = PSUB(ua, uc);                                 \
    u64 t2 = PADD(ub, ud), t3 = PSUB(ub, ud);                                 \
    A = U2F(PADD(t0, t2));                                                    \
    C = U2F(PSUB(t0, t2));                                                    \
    float2 f1 = U2F(t1), f3 = U2F(t3);                                        \
    Bq = make_float2(f1.x + f3.y, f1.y - f3.x);                               \
    D  = make_float2(f1.x - f3.y, f1.y + f3.x);                               \
} while (0)

// bin->tref-column mapping (col = k ^ 512), as tv[] index: compile-time per p
#define HCOL(p) (((((p) >> 3) & 3)) | ((((p) >> 1) & 3) << 2) | (((((p) & 1)) ^ 1) << 4))

// ---------------- radix-2 smem FFT (hilbert only) ----------------
template <bool INV>
__device__ __forceinline__ void fft1024(float2* sm, const float2* tw, int tid) {
#pragma unroll
    for (int e = 0; e < 4; e++) {
        int i = tid + e * NT;
        int j = __brev(i) >> 22;
        if (i < j) { float2 t = sm[i]; sm[i] = sm[j]; sm[j] = t; }
    }
    __syncthreads();
#pragma unroll
    for (int s = 1; s <= 10; s++) {
        int half = 1 << (s - 1);
#pragma unroll
        for (int e = 0; e < 2; e++) {
            int m   = tid + e * NT;
            int pos = m & (half - 1);
            int i0  = ((m >> (s - 1)) << s) + pos;
            int i1  = i0 + half;
            float2 w = tw[pos << (10 - s)];
            float wy = INV ? -w.y : w.y;
            float2 q = sm[i1];
            float2 v = make_float2(q.x * w.x - q.y * wy, q.x * wy + q.y * w.x);
            float2 u = sm[i0];
            sm[i0] = make_float2(u.x + v.x, u.y + v.y);
            sm[i1] = make_float2(u.x - v.x, u.y - v.y);
        }
        __syncthreads();
    }
    if (INV) {
        const float sc = 1.0f / (float)NN;
#pragma unroll
        for (int e = 0; e < 4; e++) { int i = tid + e * NT; sm[i].x *= sc; sm[i].y *= sc; }
        __syncthreads();
    }
}

// ---------------- kernel 1: init ----------------
__global__ void init_kernel() {
    int t = threadIdx.x;   // 1024 threads
    if (t < BB) {
        g_accS[t] = 0.0; g_accST[t] = 0.0; g_accT[t] = 0.0; g_accT2[t] = 0.0;
        g_accMax[t] = 0u;
    }
    double ang = -2.0 * 3.14159265358979323846 * (double)t / (double)NN;
    g_tw[t] = make_float2((float)cos(ang), (float)sin(ang));
}

// ---------------- kernel 2: hilbert + modulation ----------------
__global__ void hilbert_kernel(const float* __restrict__ pred) {
    __shared__ float2 sm[NN];
    __shared__ float2 tw[NN / 2];
    int b = blockIdx.x, tid = threadIdx.x;
#pragma unroll
    for (int e = 0; e < 2; e++) tw[tid + e * NT] = g_tw[tid + e * NT];
#pragma unroll
    for (int e = 0; e < 4; e++) {
        int i = tid + e * NT;
        sm[i] = make_float2(pred[b * NN + i], 0.0f);
    }
    __syncthreads();
    fft1024<false>(sm, tw, tid);
#pragma unroll
    for (int e = 0; e < 4; e++) {
        int i = tid + e * NT;
        float h = (i < NN / 2) ? 0.0f : ((i == NN / 2) ? 1.0f : 2.0f);
        sm[i].x *= h; sm[i].y *= h;
    }
    __syncthreads();
    fft1024<true>(sm, tw, tid);
#pragma unroll
    for (int e = 0; e < 4; e++) {
        int i = tid + e * NT;
        float2 a = sm[i];
        g_pa[b * NN + i] = a;
        float ang = (float)(2.0 * 1175000000000000.0 * 1.5e-15 * (double)(i - 512));
        float cs = cosf(ang), sn = sinf(ang);
        g_pam[b * NN + i] = cmulf(a, make_float2(cs, -sn));
    }
}

// ---------------- kernel 3: MSE partials ----------------
__global__ void mse_kernel(const float* __restrict__ label) {
    int b = blockIdx.x, tid = threadIdx.x;
    const float* lr = label + (size_t)b * 2 * NN;
    const float* li = lr + NN;

    __shared__ int s_frR, s_laR, s_frI, s_laI;
    if (tid == 0) { s_frR = NN; s_laR = -1; s_frI = NN; s_laI = -1; }
    __syncthreads();
    int frR = NN, laR = -1, frI = NN, laI = -1;
    for (int t = tid; t < NN; t += NT) {
        if (fabsf(lr[t]) > 0.01f) { frR = min(frR, t); laR = max(laR, t); }
        if (fabsf(li[t]) > 0.01f) { frI = min(frI, t); laI = max(laI, t); }
    }
    atomicMin(&s_frR, frR); atomicMax(&s_laR, laR);
    atomicMin(&s_frI, frI); atomicMax(&s_laI, laI);
    __syncthreads();
    int fr_r = (s_frR == NN) ? 0 : s_frR;
    int la_r = (s_laR < 0) ? (NN - 1) : s_laR;
    int fr_i = (s_frI == NN) ? 0 : s_frI;
    int la_i = (s_laI < 0) ? (NN - 1) : s_laI;
    int first = min(fr_r, fr_i);
    int last  = max(la_r, la_i);

    float sR = 0, sI = 0, sInt = 0, sPh = 0;
    for (int t = tid; t < NN; t += NT) {
        float2 p = g_pa[b * NN + t];
        float LR = lr[t], LI = li[t];
        bool inr = (t >= first) && (t < last);
        float pm = inr ? 10.0f : 1.0f;
        float dr = p.x - LR, di = p.y - LI;
        float pint = p.x * p.x + p.y * p.y;
        float lint = LR * LR + LI * LI;
        float dint = pint - lint;
        sR   += dr * dr * pm;
        sI   += di * di * pm;
        sInt += dint * dint * pm;
        if (inr) {
            float dp = atan2f(p.y, p.x) - atan2f(LI, LR);
            sPh += dp * dp;
        }
    }
    float tot = sR + sI + sInt + sPh;
#pragma unroll
    for (int o = 16; o > 0; o >>= 1) tot += __shfl_down_sync(0xffffffffu, tot, o);
    __shared__ float rA[8];
    int w = tid >> 5, lane = tid & 31;
    if (lane == 0) rA[w] = tot;
    __syncthreads();
    if (tid == 0) {
        float a = 0;
#pragma unroll
        for (int i = 0; i < 8; i++) a += rA[i];
        g_mse[b] = a * (1.0f / NN) * 0.25f;
    }
}

// ---------------- kernel 4: SHG, warp-autonomous 1024-pt FFT ----------------
// 32 threads per FFT (1 warp), 32 elements/thread, single padded transpose,
// no cross-warp barriers. DT2 scaling dropped (cancels in frog: only S/M used).
#define TPAD 1056   // 33*32 float2 per warp

__global__ __launch_bounds__(256, 2) void shg_kernel(const float* __restrict__ tref) {
    extern __shared__ char sraw[];
    float2* paS2    = (float2*)sraw;        // 2048 (16KB, duplicated)
    float2* pamS    = paS2 + 2 * NN;        // 1024 (8KB)
    float2* twS     = pamS + NN;            // 1024 (8KB, full table)
    float2* tbufAll = twS + 1024;           // 8 * 1056 (66KB)

    int tid = threadIdx.x;
    int b = blockIdx.y;
    int wid = tid >> 5, lt = tid & 31;
    float2* tbuf = tbufAll + wid * TPAD;

    for (int i = tid; i < NN; i += NT) {
        float2 v = g_pa[b * NN + i];
        paS2[i] = v; paS2[i + NN] = v;
        pamS[i] = g_pam[b * NN + i];
    }
    for (int i = tid; i < 1024; i += NT) twS[i] = g_tw[i];
    __syncthreads();

    const float* base = tref + (size_t)b * NN * NN;
    const int kb = ((lt >> 3) & 3) | (((lt >> 1) & 3) << 2) | ((lt & 1) << 4);

    float lmax = 0.0f;
    double dS = 0.0, dST = 0.0, dT = 0.0, dT2a = 0.0;

    for (int rr = 0; rr < 4; rr++) {
        int d = blockIdx.x * 32 + wid * 4 + rr;   // 0..1023
        int delay = d - 512;
        int tb = (lt - delay) & (NN - 1);

        // tref loads issued first: each instruction's 32 lanes hit one 128B line
        const float* rowp = base + (size_t)d * NN + kb;
        float tv[32];
#pragma unroll
        for (int m = 0; m < 32; m++) tv[m] = rowp[32 * m];

        // input build, layout: r[e] = c[lt + 32e]
        float2 r[32];
#pragma unroll
        for (int e = 0; e < 32; e++)
            r[e] = cmulf(pamS[lt + 32 * e], paS2[tb + 32 * e]);

        // stage A (L=1024, radix-4): q = lt+32e0; w1,w2,w3 direct from table
#pragma unroll
        for (int e0 = 0; e0 < 8; e0++) {
            int q = lt + 32 * e0;
            float2 w1 = twS[q], w2 = twS[2 * q], w3 = twS[3 * q];
            BFLY4P(r[e0], r[e0 + 8], r[e0 + 16], r[e0 + 24], w1, w2, w3);
        }
        // stage B (L=256, radix-4): q = 4*(lt+32e1); table lookups
#pragma unroll
        for (int e1 = 0; e1 < 2; e1++) {
            int q = 4 * lt + 128 * e1;
            float2 w1 = twS[q], w2 = twS[2 * q], w3 = twS[3 * q];
#pragma unroll
            for (int blk = 0; blk < 4; blk++) {
                int q0 = 8 * blk + e1;
                BFLY4P(r[q0], r[q0 + 2], r[q0 + 4], r[q0 + 6], w1, w2, w3);
            }
        }
        // stage C (L=64, radix-2): w = W_64^lt = W_1024^{16lt}
        {
            float2 wc = twS[16 * lt];
#pragma unroll
            for (int e = 0; e < 32; e += 2) {
                u64 ua = F2U(r[e]), ub = F2U(r[e + 1]);
                r[e] = U2F(PADD(ua, ub));
                float2 dd = U2F(PSUB(ua, ub));
                r[e + 1] = make_float2(dd.x * wc.x - dd.y * wc.y,
                                       dd.x * wc.y + dd.y * wc.x);
            }
        }
        // transpose (padded, conflict-free)
#pragma unroll
        for (int e = 0; e < 32; e++) tbuf[33 * lt + e] = r[e];
        __syncwarp();
#pragma unroll
        for (int p = 0; p < 32; p++) r[p] = tbuf[33 * p + lt];
        __syncwarp();

        // stage D (L=32, radix-4): constant twiddles W_32; p0=0 identity
        {
            const float2 WD1[8] = {{1.f,0.f},{0.98078528f,-0.19509032f},{0.92387953f,-0.38268343f},{0.83146961f,-0.55557023f},{0.70710678f,-0.70710678f},{0.55557023f,-0.83146961f},{0.38268343f,-0.92387953f},{0.19509032f,-0.98078528f}};
            const float2 WD2[8] = {{1.f,0.f},{0.92387953f,-0.38268343f},{0.70710678f,-0.70710678f},{0.38268343f,-0.92387953f},{0.f,-1.f},{-0.38268343f,-0.92387953f},{-0.70710678f,-0.70710678f},{-0.92387953f,-0.38268343f}};
            const float2 WD3[8] = {{1.f,0.f},{0.83146961f,-0.55557023f},{0.38268343f,-0.92387953f},{-0.19509032f,-0.98078528f},{-0.70710678f,-0.70710678f},{-0.98078528f,-0.19509032f},{-0.92387953f,0.38268343f},{-0.55557023f,0.83146961f}};
            BFLY4P0(r[0], r[8], r[16], r[24]);
#pragma unroll
            for (int p0 = 1; p0 < 8; p0++)
                BFLY4P(r[p0], r[p0 + 8], r[p0 + 16], r[p0 + 24], WD1[p0], WD2[p0], WD3[p0]);
        }
        // stage E (L=8, radix-4): q=0 identity, q=1 constant
        {
            const float2 WE1 = {0.70710678f, -0.70710678f};
            const float2 WE2 = {0.f, -1.f};
            const float2 WE3 = {-0.70710678f, -0.70710678f};
#pragma unroll
            for (int pb = 0; pb < 32; pb += 8) {
                BFLY4P0(r[pb + 0], r[pb + 2], r[pb + 4], r[pb + 6]);
                BFLY4P(r[pb + 1], r[pb + 3], r[pb + 5], r[pb + 7], WE1, WE2, WE3);
            }
        }
        // stage F (L=2) + magnitudes (raw, no DT2) + fused reductions
        float rS = 0.0f, rST = 0.0f;
#pragma unroll
        for (int h = 0; h < 16; h++) {
            u64 ua = F2U(r[2 * h]), ub = F2U(r[2 * h + 1]);
            float2 y0 = U2F(PADD(ua, ub));
            float2 y1 = U2F(PSUB(ua, ub));
            float s0 = y0.x * y0.x + y0.y * y0.y;
            float s1 = y1.x * y1.x + y1.y * y1.y;
            lmax = fmaxf(lmax, fmaxf(s0, s1));
            rS += s0 + s1;
            rST += s0 * tv[HCOL(2 * h)] + s1 * tv[HCOL(2 * h + 1)];
        }
        float rT = 0.0f, rT2 = 0.0f;
#pragma unroll
        for (int m = 0; m < 32; m++) { rT += tv[m]; rT2 += tv[m] * tv[m]; }

        dS += rS; dST += rST; dT += rT; dT2a += rT2;
    }

    // block reduction
    double vS = dS, vST = dST, vT = dT, vT2 = dT2a; float vM = lmax;
#pragma unroll
    for (int o = 16; o > 0; o >>= 1) {
        vS  += __shfl_down_sync(0xffffffffu, vS,  o);
        vST += __shfl_down_sync(0xffffffffu, vST, o);
        vT  += __shfl_down_sync(0xffffffffu, vT,  o);
        vT2 += __shfl_down_sync(0xffffffffu, vT2, o);
        vM   = fmaxf(vM, __shfl_down_sync(0xffffffffu, vM, o));
    }
    __shared__ double sS[8], sST[8], sT[8], sT2[8];
    __shared__ float  sM[8];
    if (lt == 0) { sS[wid] = vS; sST[wid] = vST; sT[wid] = vT; sT2[wid] = vT2; sM[wid] = vM; }
    __syncthreads();
    if (tid == 0) {
        double aS = 0, aST = 0, aT = 0, aT2 = 0; float aM = 0.0f;
#pragma unroll
        for (int i = 0; i < 8; i++) {
            aS += sS[i]; aST += sST[i]; aT += sT[i]; aT2 += sT2[i];
            aM = fmaxf(aM, sM[i]);
        }
        atomicAdd(&g_accS[b],  aS);
        atomicAdd(&g_accST[b], aST);
        atomicAdd(&g_accT[b],  aT);
        atomicAdd(&g_accT2[b], aT2);
        atomicMax(&g_accMax[b], __float_as_uint(aM));
    }
}

// ---------------- kernel 5: frog + final mean ----------------
// All S values are raw (DT2-free); frog uses only S/M so the scale cancels.
__global__ void finalize_kernel(float* out) {
    int b = threadIdx.x;   // 32 threads
    double M    = (double)__uint_as_float(g_accMax[b]);
    double sum1 = g_accST[b] / M;
    double mu   = sum1 / g_accT2[b];
    double diff = g_accS[b] / M - mu * g_accT[b];
    double r2   = diff * diff;
    float frog  = (r2 == 0.0) ? 0.0f : (float)(sqrt(r2) / (double)NN);
    float v = g_mse[b] + frog;
#pragma unroll
    for (int o = 16; o > 0; o >>= 1) v += __shfl_down_sync(0xffffffffu, v, o);
    if (b == 0) out[0] = v * (1.0f / BB);
}

// ---------------- launch ----------------
extern "C" void kernel_launch(void* const* d_in, const int* in_sizes, int n_in,
                              void* d_out, int out_size) {
    const float* pred  = (const float*)d_in[0];
    const float* label = (const float*)d_in[1];
    const float* shg   = (const float*)d_in[2];
    float* out = (float*)d_out;

    const int SHG_SMEM = (2 * NN + NN + 1024 + 8 * TPAD) * sizeof(float2);  // ~98KB
    static int attr_done = 0;
    if (!attr_done) {
        cudaFuncSetAttribute(shg_kernel, cudaFuncAttributeMaxDynamicSharedMemorySize, SHG_SMEM);
        attr_done = 1;
    }

    init_kernel<<<1, 1024>>>();
    hilbert_kernel<<<BB, NT>>>(pred);
    mse_kernel<<<BB, NT>>>(label);
    shg_kernel<<<dim3(32, BB), NT, SHG_SMEM>>>(shg);   // node 4 -> ncu capture slot
    finalize_kernel<<<1, 32>>>(out);
}

// round 12
// speedup vs baseline: 1.0167x; 1.0167x over previous
#include <cuda_runtime.h>
#include <math.h>

#define NN 1024
#define NT 256
#define BB 32

typedef unsigned long long u64;

// ---------------- device scratch ----------------
__device__ float2   g_pa[BB * NN];
__device__ float2   g_pam[BB * NN];
__device__ float2   g_tw[1024];           // W_1024^k, full table
__device__ double   g_accS[BB], g_accST[BB], g_accT[BB], g_accT2[BB];
__device__ unsigned g_accMax[BB];
__device__ float    g_mse[BB];

__device__ __forceinline__ float2 cmulf(float2 a, float2 b) {
    return make_float2(a.x * b.x - a.y * b.y, a.x * b.y + a.y * b.x);
}

// ---------------- packed helpers (one complex value per u64) ----------------
__device__ __forceinline__ u64 F2U(float2 v) {
    u64 r; asm("mov.b64 %0,{%1,%2};" : "=l"(r) : "f"(v.x), "f"(v.y)); return r;
}
__device__ __forceinline__ float2 U2F(u64 v) {
    float2 r; asm("mov.b64 {%0,%1},%2;" : "=f"(r.x), "=f"(r.y) : "l"(v)); return r;
}
__device__ __forceinline__ u64 PADD(u64 a, u64 b) {
    u64 r; asm("add.rn.f32x2 %0,%1,%2;" : "=l"(r) : "l"(a), "l"(b)); return r;
}
__device__ __forceinline__ u64 PSUB(u64 a, u64 b) {
    const u64 n1 = 0xBF800000BF800000ULL;
    u64 r; asm("fma.rn.f32x2 %0,%1,%2,%3;" : "=l"(r) : "l"(b), "l"(n1), "l"(a)); return r;
}

// radix-4 DIF butterfly: packed adds, scalar cross-terms + cmuls
#define BFLY4P(A, Bq, C, D, W1, W2, W3) do {                                  \
    u64 ua = F2U(A), ub = F2U(Bq), uc = F2U(C), ud = F2U(D);                  \
    u64 t0 = PADD(ua, uc), t1 = PSUB(ua, uc);                                 \
    u64 t2 = PADD(ub, ud), t3 = PSUB(ub, ud);                                 \
    A = U2F(PADD(t0, t2));                                                    \
    float2 ci = U2F(PSUB(t0, t2));                                            \
    float2 f1 = U2F(t1), f3 = U2F(t3);                                        \
    float bx = f1.x + f3.y, by = f1.y - f3.x;                                 \
    float dx = f1.x - f3.y, dy = f1.y + f3.x;                                 \
    Bq = make_float2(bx * W1.x - by * W1.y, bx * W1.y + by * W1.x);           \
    C  = make_float2(ci.x * W2.x - ci.y * W2.y, ci.x * W2.y + ci.y * W2.x);   \
    D  = make_float2(dx * W3.x - dy * W3.y, dx * W3.y + dy * W3.x);           \
} while (0)

// identity-twiddle butterfly (W1=W2=W3=1): pure adds
#define BFLY4P0(A, Bq, C, D) do {                                             \
    u64 ua = F2U(A), ub = F2U(Bq), uc = F2U(C), ud = F2U(D);                  \
    u64 t0 = PADD(ua, uc), t1 = PSUB(ua, uc);                                 \
    u64 t2 = PADD(ub, ud), t3 = PSUB(ub, ud);                                 \
    A = U2F(PADD(t0, t2));                                                    \
    C = U2F(PSUB(t0, t2));                                                    \
    float2 f1 = U2F(t1), f3 = U2F(t3);                                        \
    Bq = make_float2(f1.x + f3.y, f1.y - f3.x);                               \
    D  = make_float2(f1.x - f3.y, f1.y + f3.x);                               \
} while (0)

// bin->tref-column mapping (col = k ^ 512), as tv[] index: compile-time per p
#define HCOL(p) (((((p) >> 3) & 3)) | ((((p) >> 1) & 3) << 2) | (((((p) & 1)) ^ 1) << 4))

// ---------------- radix-2 smem FFT (hilbert only) ----------------
template <bool INV>
__device__ __forceinline__ void fft1024(float2* sm, const float2* tw, int tid) {
#pragma unroll
    for (int e = 0; e < 4; e++) {
        int i = tid + e * NT;
        int j = __brev(i) >> 22;
        if (i < j) { float2 t = sm[i]; sm[i] = sm[j]; sm[j] = t; }
    }
    __syncthreads();
#pragma unroll
    for (int s = 1; s <= 10; s++) {
        int half = 1 << (s - 1);
#pragma unroll
        for (int e = 0; e < 2; e++) {
            int m   = tid + e * NT;
            int pos = m & (half - 1);
            int i0  = ((m >> (s - 1)) << s) + pos;
            int i1  = i0 + half;
            float2 w = tw[pos << (10 - s)];
            float wy = INV ? -w.y : w.y;
            float2 q = sm[i1];
            float2 v = make_float2(q.x * w.x - q.y * wy, q.x * wy + q.y * w.x);
            float2 u = sm[i0];
            sm[i0] = make_float2(u.x + v.x, u.y + v.y);
            sm[i1] = make_float2(u.x - v.x, u.y - v.y);
        }
        __syncthreads();
    }
    if (INV) {
        const float sc = 1.0f / (float)NN;
#pragma unroll
        for (int e = 0; e < 4; e++) { int i = tid + e * NT; sm[i].x *= sc; sm[i].y *= sc; }
        __syncthreads();
    }
}

// ---------------- kernel 1: init ----------------
__global__ void init_kernel() {
    int t = threadIdx.x;   // 1024 threads
    if (t < BB) {
        g_accS[t] = 0.0; g_accST[t] = 0.0; g_accT[t] = 0.0; g_accT2[t] = 0.0;
        g_accMax[t] = 0u;
    }
    double ang = -2.0 * 3.14159265358979323846 * (double)t / (double)NN;
    g_tw[t] = make_float2((float)cos(ang), (float)sin(ang));
}

// ---------------- kernel 2: hilbert + modulation ----------------
__global__ void hilbert_kernel(const float* __restrict__ pred) {
    __shared__ float2 sm[NN];
    __shared__ float2 tw[NN / 2];
    int b = blockIdx.x, tid = threadIdx.x;
#pragma unroll
    for (int e = 0; e < 2; e++) tw[tid + e * NT] = g_tw[tid + e * NT];
#pragma unroll
    for (int e = 0; e < 4; e++) {
        int i = tid + e * NT;
        sm[i] = make_float2(pred[b * NN + i], 0.0f);
    }
    __syncthreads();
    fft1024<false>(sm, tw, tid);
#pragma unroll
    for (int e = 0; e < 4; e++) {
        int i = tid + e * NT;
        float h = (i < NN / 2) ? 0.0f : ((i == NN / 2) ? 1.0f : 2.0f);
        sm[i].x *= h; sm[i].y *= h;
    }
    __syncthreads();
    fft1024<true>(sm, tw, tid);
#pragma unroll
    for (int e = 0; e < 4; e++) {
        int i = tid + e * NT;
        float2 a = sm[i];
        g_pa[b * NN + i] = a;
        float ang = (float)(2.0 * 1175000000000000.0 * 1.5e-15 * (double)(i - 512));
        float cs = cosf(ang), sn = sinf(ang);
        g_pam[b * NN + i] = cmulf(a, make_float2(cs, -sn));
    }
}

// ---------------- kernel 3: MSE partials ----------------
__global__ void mse_kernel(const float* __restrict__ label) {
    int b = blockIdx.x, tid = threadIdx.x;
    const float* lr = label + (size_t)b * 2 * NN;
    const float* li = lr + NN;

    __shared__ int s_frR, s_laR, s_frI, s_laI;
    if (tid == 0) { s_frR = NN; s_laR = -1; s_frI = NN; s_laI = -1; }
    __syncthreads();
    int frR = NN, laR = -1, frI = NN, laI = -1;
    for (int t = tid; t < NN; t += NT) {
        if (fabsf(lr[t]) > 0.01f) { frR = min(frR, t); laR = max(laR, t); }
        if (fabsf(li[t]) > 0.01f) { frI = min(frI, t); laI = max(laI, t); }
    }
    atomicMin(&s_frR, frR); atomicMax(&s_laR, laR);
    atomicMin(&s_frI, frI); atomicMax(&s_laI, laI);
    __syncthreads();
    int fr_r = (s_frR == NN) ? 0 : s_frR;
    int la_r = (s_laR < 0) ? (NN - 1) : s_laR;
    int fr_i = (s_frI == NN) ? 0 : s_frI;
    int la_i = (s_laI < 0) ? (NN - 1) : s_laI;
    int first = min(fr_r, fr_i);
    int last  = max(la_r, la_i);

    float sR = 0, sI = 0, sInt = 0, sPh = 0;
    for (int t = tid; t < NN; t += NT) {
        float2 p = g_pa[b * NN + t];
        float LR = lr[t], LI = li[t];
        bool inr = (t >= first) && (t < last);
        float pm = inr ? 10.0f : 1.0f;
        float dr = p.x - LR, di = p.y - LI;
        float pint = p.x * p.x + p.y * p.y;
        float lint = LR * LR + LI * LI;
        float dint = pint - lint;
        sR   += dr * dr * pm;
        sI   += di * di * pm;
        sInt += dint * dint * pm;
        if (inr) {
            float dp = atan2f(p.y, p.x) - atan2f(LI, LR);
            sPh += dp * dp;
        }
    }
    float tot = sR + sI + sInt + sPh;
#pragma unroll
    for (int o = 16; o > 0; o >>= 1) tot += __shfl_down_sync(0xffffffffu, tot, o);
    __shared__ float rA[8];
    int w = tid >> 5, lane = tid & 31;
    if (lane == 0) rA[w] = tot;
    __syncthreads();
    if (tid == 0) {
        float a = 0;
#pragma unroll
        for (int i = 0; i < 8; i++) a += rA[i];
        g_mse[b] = a * (1.0f / NN) * 0.25f;
    }
}

// ---------------- kernel 4: SHG, warp-autonomous 1024-pt FFT ----------------
// Conflict-free stride-1 twiddle tables; stage-C twiddle hoisted to register.
#define TPAD 1056   // 33*32 float2 per warp

__global__ __launch_bounds__(256, 2) void shg_kernel(const float* __restrict__ tref) {
    extern __shared__ char sraw[];
    float2* paS2    = (float2*)sraw;        // 2048 (16KB, duplicated)
    float2* pamS    = paS2 + 2 * NN;        // 1024 (8KB)
    float2* twA1    = pamS + NN;            // 256
    float2* twA2    = twA1 + 256;           // 256
    float2* twA3    = twA2 + 256;           // 256
    float2* twB1    = twA3 + 256;           // 64
    float2* twB2    = twB1 + 64;            // 64
    float2* twB3    = twB2 + 64;            // 64
    float2* tbufAll = twB3 + 64;            // 8 * 1056 (66KB)

    int tid = threadIdx.x;
    int b = blockIdx.y;
    int wid = tid >> 5, lt = tid & 31;
    float2* tbuf = tbufAll + wid * TPAD;

    for (int i = tid; i < NN; i += NT) {
        float2 v = g_pa[b * NN + i];
        paS2[i] = v; paS2[i + NN] = v;
        pamS[i] = g_pam[b * NN + i];
    }
    if (tid < 256) {
        twA1[tid] = g_tw[tid];
        twA2[tid] = g_tw[2 * tid];
        twA3[tid] = g_tw[3 * tid];
    }
    if (tid < 64) {
        twB1[tid] = g_tw[4 * tid];
        twB2[tid] = g_tw[8 * tid];
        twB3[tid] = g_tw[12 * tid];
    }
    __syncthreads();

    const float* base = tref + (size_t)b * NN * NN;
    const int kb = ((lt >> 3) & 3) | (((lt >> 1) & 3) << 2) | ((lt & 1) << 4);
    const float2 wc = g_tw[16 * lt];   // stage-C twiddle, loop-invariant

    float lmax = 0.0f;
    double dS = 0.0, dST = 0.0, dT = 0.0, dT2a = 0.0;

    for (int rr = 0; rr < 4; rr++) {
        int d = blockIdx.x * 32 + wid * 4 + rr;   // 0..1023
        int delay = d - 512;
        int tb = (lt - delay) & (NN - 1);

        // tref loads issued first: each instruction's 32 lanes hit one 128B line
        const float* rowp = base + (size_t)d * NN + kb;
        float tv[32];
#pragma unroll
        for (int m = 0; m < 32; m++) tv[m] = rowp[32 * m];

        // input build, layout: r[e] = c[lt + 32e]
        float2 r[32];
#pragma unroll
        for (int e = 0; e < 32; e++)
            r[e] = cmulf(pamS[lt + 32 * e], paS2[tb + 32 * e]);

        // stage A (L=1024, radix-4): q = lt+32e0; stride-1 table lookups
#pragma unroll
        for (int e0 = 0; e0 < 8; e0++) {
            int q = lt + 32 * e0;
            float2 w1 = twA1[q], w2 = twA2[q], w3 = twA3[q];
            BFLY4P(r[e0], r[e0 + 8], r[e0 + 16], r[e0 + 24], w1, w2, w3);
        }
        // stage B (L=256, radix-4): i = lt+32e1 (q = 4i); stride-1 lookups
#pragma unroll
        for (int e1 = 0; e1 < 2; e1++) {
            int i = lt + 32 * e1;
            float2 w1 = twB1[i], w2 = twB2[i], w3 = twB3[i];
#pragma unroll
            for (int blk = 0; blk < 4; blk++) {
                int q0 = 8 * blk + e1;
                BFLY4P(r[q0], r[q0 + 2], r[q0 + 4], r[q0 + 6], w1, w2, w3);
            }
        }
        // stage C (L=64, radix-2): hoisted register twiddle
#pragma unroll
        for (int e = 0; e < 32; e += 2) {
            u64 ua = F2U(r[e]), ub = F2U(r[e + 1]);
            r[e] = U2F(PADD(ua, ub));
            float2 dd = U2F(PSUB(ua, ub));
            r[e + 1] = make_float2(dd.x * wc.x - dd.y * wc.y,
                                   dd.x * wc.y + dd.y * wc.x);
        }
        // transpose (padded, conflict-free)
#pragma unroll
        for (int e = 0; e < 32; e++) tbuf[33 * lt + e] = r[e];
        __syncwarp();
#pragma unroll
        for (int p = 0; p < 32; p++) r[p] = tbuf[33 * p + lt];
        __syncwarp();

        // stage D (L=32, radix-4): constant twiddles W_32; p0=0 identity
        {
            const float2 WD1[8] = {{1.f,0.f},{0.98078528f,-0.19509032f},{0.92387953f,-0.38268343f},{0.83146961f,-0.55557023f},{0.70710678f,-0.70710678f},{0.55557023f,-0.83146961f},{0.38268343f,-0.92387953f},{0.19509032f,-0.98078528f}};
            const float2 WD2[8] = {{1.f,0.f},{0.92387953f,-0.38268343f},{0.70710678f,-0.70710678f},{0.38268343f,-0.92387953f},{0.f,-1.f},{-0.38268343f,-0.92387953f},{-0.70710678f,-0.70710678f},{-0.92387953f,-0.38268343f}};
            const float2 WD3[8] = {{1.f,0.f},{0.83146961f,-0.55557023f},{0.38268343f,-0.92387953f},{-0.19509032f,-0.98078528f},{-0.70710678f,-0.70710678f},{-0.98078528f,-0.19509032f},{-0.92387953f,0.38268343f},{-0.55557023f,0.83146961f}};
            BFLY4P0(r[0], r[8], r[16], r[24]);
#pragma unroll
            for (int p0 = 1; p0 < 8; p0++)
                BFLY4P(r[p0], r[p0 + 8], r[p0 + 16], r[p0 + 24], WD1[p0], WD2[p0], WD3[p0]);
        }
        // stage E (L=8, radix-4): q=0 identity, q=1 constant
        {
            const float2 WE1 = {0.70710678f, -0.70710678f};
            const float2 WE2 = {0.f, -1.f};
            const float2 WE3 = {-0.70710678f, -0.70710678f};
#pragma unroll
            for (int pb = 0; pb < 32; pb += 8) {
                BFLY4P0(r[pb + 0], r[pb + 2], r[pb + 4], r[pb + 6]);
                BFLY4P(r[pb + 1], r[pb + 3], r[pb + 5], r[pb + 7], WE1, WE2, WE3);
            }
        }
        // stage F (L=2) + magnitudes + fused reductions
        float rS = 0.0f, rST = 0.0f;
#pragma unroll
        for (int h = 0; h < 16; h++) {
            u64 ua = F2U(r[2 * h]), ub = F2U(r[2 * h + 1]);
            float2 y0 = U2F(PADD(ua, ub));
            float2 y1 = U2F(PSUB(ua, ub));
            float s0 = y0.x * y0.x + y0.y * y0.y;
            float s1 = y1.x * y1.x + y1.y * y1.y;
            lmax = fmaxf(lmax, fmaxf(s0, s1));
            rS += s0 + s1;
            rST += s0 * tv[HCOL(2 * h)] + s1 * tv[HCOL(2 * h + 1)];
        }
        float rT = 0.0f, rT2 = 0.0f;
#pragma unroll
        for (int m = 0; m < 32; m++) { rT += tv[m]; rT2 += tv[m] * tv[m]; }

        dS += rS; dST += rST; dT += rT; dT2a += rT2;
    }

    // block reduction
    double vS = dS, vST = dST, vT = dT, vT2 = dT2a; float vM = lmax;
#pragma unroll
    for (int o = 16; o > 0; o >>= 1) {
        vS  += __shfl_down_sync(0xffffffffu, vS,  o);
        vST += __shfl_down_sync(0xffffffffu, vST, o);
        vT  += __shfl_down_sync(0xffffffffu, vT,  o);
        vT2 += __shfl_down_sync(0xffffffffu, vT2, o);
        vM   = fmaxf(vM, __shfl_down_sync(0xffffffffu, vM, o));
    }
    __shared__ double sS[8], sST[8], sT[8], sT2[8];
    __shared__ float  sM[8];
    if (lt == 0) { sS[wid] = vS; sST[wid] = vST; sT[wid] = vT; sT2[wid] = vT2; sM[wid] = vM; }
    __syncthreads();
    if (tid == 0) {
        double aS = 0, aST = 0, aT = 0, aT2 = 0; float aM = 0.0f;
#pragma unroll
        for (int i = 0; i < 8; i++) {
            aS += sS[i]; aST += sST[i]; aT += sT[i]; aT2 += sT2[i];
            aM = fmaxf(aM, sM[i]);
        }
        atomicAdd(&g_accS[b],  aS);
        atomicAdd(&g_accST[b], aST);
        atomicAdd(&g_accT[b],  aT);
        atomicAdd(&g_accT2[b], aT2);
        atomicMax(&g_accMax[b], __float_as_uint(aM));
    }
}

// ---------------- kernel 5: frog + final mean ----------------
__global__ void finalize_kernel(float* out) {
    int b = threadIdx.x;   // 32 threads
    double M    = (double)__uint_as_float(g_accMax[b]);
    double sum1 = g_accST[b] / M;
    double mu   = sum1 / g_accT2[b];
    double diff = g_accS[b] / M - mu * g_accT[b];
    double r2   = diff * diff;
    float frog  = (r2 == 0.0) ? 0.0f : (float)(sqrt(r2) / (double)NN);
    float v = g_mse[b] + frog;
#pragma unroll
    for (int o = 16; o > 0; o >>= 1) v += __shfl_down_sync(0xffffffffu, v, o);
    if (b == 0) out[0] = v * (1.0f / BB);
}

// ---------------- launch ----------------
extern "C" void kernel_launch(void* const* d_in, const int* in_sizes, int n_in,
                              void* d_out, int out_size) {
    const float* pred  = (const float*)d_in[0];
    const float* label = (const float*)d_in[1];
    const float* shg   = (const float*)d_in[2];
    float* out = (float*)d_out;

    const int SHG_SMEM = (2 * NN + NN + 3 * 256 + 3 * 64 + 8 * TPAD) * sizeof(float2);
    static int attr_done = 0;
    if (!attr_done) {
        cudaFuncSetAttribute(shg_kernel, cudaFuncAttributeMaxDynamicSharedMemorySize, SHG_SMEM);
        attr_done = 1;
    }

    init_kernel<<<1, 1024>>>();
    hilbert_kernel<<<BB, NT>>>(pred);
    mse_kernel<<<BB, NT>>>(label);
    shg_kernel<<<dim3(32, BB), NT, SHG_SMEM>>>(shg);   // node 4 -> ncu capture slot
    finalize_kernel<<<1, 32>>>(out);
}

// round 13
// speedup vs baseline: 1.0195x; 1.0027x over previous
#include <cuda_runtime.h>
#include <math.h>

#define NN 1024
#define NT 256
#define BB 32

typedef unsigned long long u64;

// ---------------- device scratch ----------------
__device__ float2   g_pa[BB * NN];
__device__ float2   g_pam[BB * NN];
__device__ float2   g_tw[1024];           // W_1024^k, full table
__device__ double   g_accS[BB], g_accST[BB], g_accT[BB], g_accT2[BB];
__device__ unsigned g_accMax[BB];
__device__ float    g_mse[BB];

__device__ __forceinline__ float2 cmulf(float2 a, float2 b) {
    return make_float2(a.x * b.x - a.y * b.y, a.x * b.y + a.y * b.x);
}

// ---------------- packed helpers (one complex value per u64) ----------------
__device__ __forceinline__ u64 F2U(float2 v) {
    u64 r; asm("mov.b64 %0,{%1,%2};" : "=l"(r) : "f"(v.x), "f"(v.y)); return r;
}
__device__ __forceinline__ float2 U2F(u64 v) {
    float2 r; asm("mov.b64 {%0,%1},%2;" : "=f"(r.x), "=f"(r.y) : "l"(v)); return r;
}
__device__ __forceinline__ u64 PADD(u64 a, u64 b) {
    u64 r; asm("add.rn.f32x2 %0,%1,%2;" : "=l"(r) : "l"(a), "l"(b)); return r;
}
__device__ __forceinline__ u64 PSUB(u64 a, u64 b) {
    const u64 n1 = 0xBF800000BF800000ULL;
    u64 r; asm("fma.rn.f32x2 %0,%1,%2,%3;" : "=l"(r) : "l"(b), "l"(n1), "l"(a)); return r;
}

// radix-4 DIF butterfly: packed adds, scalar cross-terms + cmuls
#define BFLY4P(A, Bq, C, D, W1, W2, W3) do {                                  \
    u64 ua = F2U(A), ub = F2U(Bq), uc = F2U(C), ud = F2U(D);                  \
    u64 t0 = PADD(ua, uc), t1 = PSUB(ua, uc);                                 \
    u64 t2 = PADD(ub, ud), t3 = PSUB(ub, ud);                                 \
    A = U2F(PADD(t0, t2));                                                    \
    float2 ci = U2F(PSUB(t0, t2));                                            \
    float2 f1 = U2F(t1), f3 = U2F(t3);                                        \
    float bx = f1.x + f3.y, by = f1.y - f3.x;                                 \
    float dx = f1.x - f3.y, dy = f1.y + f3.x;                                 \
    Bq = make_float2(bx * W1.x - by * W1.y, bx * W1.y + by * W1.x);           \
    C  = make_float2(ci.x * W2.x - ci.y * W2.y, ci.x * W2.y + ci.y * W2.x);   \
    D  = make_float2(dx * W3.x - dy * W3.y, dx * W3.y + dy * W3.x);           \
} while (0)

// identity-twiddle butterfly (W1=W2=W3=1): pure adds
#define BFLY4P0(A, Bq, C, D) do {                                             \
    u64 ua = F2U(A), ub = F2U(Bq), uc = F2U(C), ud = F2U(D);                  \
    u64 t0 = PADD(ua, uc), t1 = PSUB(ua, uc);                                 \
    u64 t2 = PADD(ub, ud), t3 = PSUB(ub, ud);                                 \
    A = U2F(PADD(t0, t2));                                                    \
    C = U2F(PSUB(t0, t2));                                                    \
    float2 f1 = U2F(t1), f3 = U2F(t3);                                        \
    Bq = make_float2(f1.x + f3.y, f1.y - f3.x);                               \
    D  = make_float2(f1.x - f3.y, f1.y + f3.x);                               \
} while (0)

// bin->tref-column mapping (col = k ^ 512), as tv[] index: compile-time per p
#define HCOL(p) (((((p) >> 3) & 3)) | ((((p) >> 1) & 3) << 2) | (((((p) & 1)) ^ 1) << 4))

// ---------------- radix-2 smem FFT (hilbert only) ----------------
template <bool INV>
__device__ __forceinline__ void fft1024(float2* sm, const float2* tw, int tid) {
#pragma unroll
    for (int e = 0; e < 4; e++) {
        int i = tid + e * NT;
        int j = __brev(i) >> 22;
        if (i < j) { float2 t = sm[i]; sm[i] = sm[j]; sm[j] = t; }
    }
    __syncthreads();
#pragma unroll
    for (int s = 1; s <= 10; s++) {
        int half = 1 << (s - 1);
#pragma unroll
        for (int e = 0; e < 2; e++) {
            int m   = tid + e * NT;
            int pos = m & (half - 1);
            int i0  = ((m >> (s - 1)) << s) + pos;
            int i1  = i0 + half;
            float2 w = tw[pos << (10 - s)];
            float wy = INV ? -w.y : w.y;
            float2 q = sm[i1];
            float2 v = make_float2(q.x * w.x - q.y * wy, q.x * wy + q.y * w.x);
            float2 u = sm[i0];
            sm[i0] = make_float2(u.x + v.x, u.y + v.y);
            sm[i1] = make_float2(u.x - v.x, u.y - v.y);
        }
        __syncthreads();
    }
    if (INV) {
        const float sc = 1.0f / (float)NN;
#pragma unroll
        for (int e = 0; e < 4; e++) { int i = tid + e * NT; sm[i].x *= sc; sm[i].y *= sc; }
        __syncthreads();
    }
}

// ---------------- kernel 1: hilbert + modulation + (block 0: init globals) ----------------
__global__ void hilbert_kernel(const float* __restrict__ pred) {
    __shared__ float2 sm[NN];
    __shared__ float2 tw[NN / 2];
    int b = blockIdx.x, tid = threadIdx.x;

    // per-block twiddles (double-derived, matches old init precision)
#pragma unroll
    for (int e = 0; e < 2; e++) {
        int i = tid + e * NT;
        double ang = -2.0 * 3.14159265358979323846 * (double)i / (double)NN;
        tw[i] = make_float2((float)cos(ang), (float)sin(ang));
    }
    // block 0 additionally publishes the full table + zeroed accumulators for shg
    if (b == 0) {
#pragma unroll
        for (int e = 0; e < 4; e++) {
            int i = tid + e * NT;
            double ang = -2.0 * 3.14159265358979323846 * (double)i / (double)NN;
            g_tw[i] = make_float2((float)cos(ang), (float)sin(ang));
        }
        if (tid < BB) {
            g_accS[tid] = 0.0; g_accST[tid] = 0.0; g_accT[tid] = 0.0; g_accT2[tid] = 0.0;
            g_accMax[tid] = 0u;
        }
    }
#pragma unroll
    for (int e = 0; e < 4; e++) {
        int i = tid + e * NT;
        sm[i] = make_float2(pred[b * NN + i], 0.0f);
    }
    __syncthreads();
    fft1024<false>(sm, tw, tid);
#pragma unroll
    for (int e = 0; e < 4; e++) {
        int i = tid + e * NT;
        float h = (i < NN / 2) ? 0.0f : ((i == NN / 2) ? 1.0f : 2.0f);
        sm[i].x *= h; sm[i].y *= h;
    }
    __syncthreads();
    fft1024<true>(sm, tw, tid);
#pragma unroll
    for (int e = 0; e < 4; e++) {
        int i = tid + e * NT;
        float2 a = sm[i];
        g_pa[b * NN + i] = a;
        float ang = (float)(2.0 * 1175000000000000.0 * 1.5e-15 * (double)(i - 512));
        float cs = cosf(ang), sn = sinf(ang);
        g_pam[b * NN + i] = cmulf(a, make_float2(cs, -sn));
    }
}

// ---------------- mse body (runs inside the fused shg launch) ----------------
__device__ void mse_body(const float* __restrict__ label, int b, int tid) {
    const float* lr = label + (size_t)b * 2 * NN;
    const float* li = lr + NN;

    __shared__ int s_frR, s_laR, s_frI, s_laI;
    if (tid == 0) { s_frR = NN; s_laR = -1; s_frI = NN; s_laI = -1; }
    __syncthreads();
    int frR = NN, laR = -1, frI = NN, laI = -1;
    for (int t = tid; t < NN; t += NT) {
        if (fabsf(lr[t]) > 0.01f) { frR = min(frR, t); laR = max(laR, t); }
        if (fabsf(li[t]) > 0.01f) { frI = min(frI, t); laI = max(laI, t); }
    }
    atomicMin(&s_frR, frR); atomicMax(&s_laR, laR);
    atomicMin(&s_frI, frI); atomicMax(&s_laI, laI);
    __syncthreads();
    int fr_r = (s_frR == NN) ? 0 : s_frR;
    int la_r = (s_laR < 0) ? (NN - 1) : s_laR;
    int fr_i = (s_frI == NN) ? 0 : s_frI;
    int la_i = (s_laI < 0) ? (NN - 1) : s_laI;
    int first = min(fr_r, fr_i);
    int last  = max(la_r, la_i);

    float sR = 0, sI = 0, sInt = 0, sPh = 0;
    for (int t = tid; t < NN; t += NT) {
        float2 p = g_pa[b * NN + t];
        float LR = lr[t], LI = li[t];
        bool inr = (t >= first) && (t < last);
        float pm = inr ? 10.0f : 1.0f;
        float dr = p.x - LR, di = p.y - LI;
        float pint = p.x * p.x + p.y * p.y;
        float lint = LR * LR + LI * LI;
        float dint = pint - lint;
        sR   += dr * dr * pm;
        sI   += di * di * pm;
        sInt += dint * dint * pm;
        if (inr) {
            float dp = atan2f(p.y, p.x) - atan2f(LI, LR);
            sPh += dp * dp;
        }
    }
    float tot = sR + sI + sInt + sPh;
#pragma unroll
    for (int o = 16; o > 0; o >>= 1) tot += __shfl_down_sync(0xffffffffu, tot, o);
    __shared__ float rA[8];
    int w = tid >> 5, lane = tid & 31;
    if (lane == 0) rA[w] = tot;
    __syncthreads();
    if (tid == 0) {
        float a = 0;
#pragma unroll
        for (int i = 0; i < 8; i++) a += rA[i];
        g_mse[b] = a * (1.0f / NN) * 0.25f;
    }
}

// ---------------- kernel 2: fused SHG + MSE ----------------
// grid (33, BB): blockIdx.x < 32 -> SHG rows; blockIdx.x == 32 -> MSE for batch b.
#define TPAD 1056   // 33*32 float2 per warp

__global__ __launch_bounds__(256, 2) void shg_kernel(const float* __restrict__ tref,
                                                     const float* __restrict__ label) {
    extern __shared__ char sraw[];
    int tid = threadIdx.x;
    int b = blockIdx.y;

    if (blockIdx.x == 32) { mse_body(label, b, tid); return; }

    float2* paS2    = (float2*)sraw;        // 2048 (16KB, duplicated)
    float2* pamS    = paS2 + 2 * NN;        // 1024 (8KB)
    float2* twA1    = pamS + NN;            // 256
    float2* twA2    = twA1 + 256;           // 256
    float2* twA3    = twA2 + 256;           // 256
    float2* twB1    = twA3 + 256;           // 64
    float2* twB2    = twB1 + 64;            // 64
    float2* twB3    = twB2 + 64;            // 64
    float2* tbufAll = twB3 + 64;            // 8 * 1056 (66KB)

    int wid = tid >> 5, lt = tid & 31;
    float2* tbuf = tbufAll + wid * TPAD;

    for (int i = tid; i < NN; i += NT) {
        float2 v = g_pa[b * NN + i];
        paS2[i] = v; paS2[i + NN] = v;
        pamS[i] = g_pam[b * NN + i];
    }
    if (tid < 256) {
        twA1[tid] = g_tw[tid];
        twA2[tid] = g_tw[2 * tid];
        twA3[tid] = g_tw[3 * tid];
    }
    if (tid < 64) {
        twB1[tid] = g_tw[4 * tid];
        twB2[tid] = g_tw[8 * tid];
        twB3[tid] = g_tw[12 * tid];
    }
    __syncthreads();

    const float* base = tref + (size_t)b * NN * NN;
    const int kb = ((lt >> 3) & 3) | (((lt >> 1) & 3) << 2) | ((lt & 1) << 4);
    const float2 wc = g_tw[16 * lt];   // stage-C twiddle, loop-invariant

    float lmax = 0.0f;
    double dS = 0.0, dST = 0.0, dT = 0.0, dT2a = 0.0;

    for (int rr = 0; rr < 4; rr++) {
        int d = blockIdx.x * 32 + wid * 4 + rr;   // 0..1023
        int delay = d - 512;
        int tb = (lt - delay) & (NN - 1);

        // tref loads issued first: each instruction's 32 lanes hit one 128B line
        const float* rowp = base + (size_t)d * NN + kb;
        float tv[32];
#pragma unroll
        for (int m = 0; m < 32; m++) tv[m] = rowp[32 * m];

        // input build, layout: r[e] = c[lt + 32e]
        float2 r[32];
#pragma unroll
        for (int e = 0; e < 32; e++)
            r[e] = cmulf(pamS[lt + 32 * e], paS2[tb + 32 * e]);

        // stage A (L=1024, radix-4): q = lt+32e0; stride-1 table lookups
#pragma unroll
        for (int e0 = 0; e0 < 8; e0++) {
            int q = lt + 32 * e0;
            float2 w1 = twA1[q], w2 = twA2[q], w3 = twA3[q];
            BFLY4P(r[e0], r[e0 + 8], r[e0 + 16], r[e0 + 24], w1, w2, w3);
        }
        // stage B (L=256, radix-4): i = lt+32e1 (q = 4i); stride-1 lookups
#pragma unroll
        for (int e1 = 0; e1 < 2; e1++) {
            int i = lt + 32 * e1;
            float2 w1 = twB1[i], w2 = twB2[i], w3 = twB3[i];
#pragma unroll
            for (int blk = 0; blk < 4; blk++) {
                int q0 = 8 * blk + e1;
                BFLY4P(r[q0], r[q0 + 2], r[q0 + 4], r[q0 + 6], w1, w2, w3);
            }
        }
        // stage C (L=64, radix-2): hoisted register twiddle
#pragma unroll
        for (int e = 0; e < 32; e += 2) {
            u64 ua = F2U(r[e]), ub = F2U(r[e + 1]);
            r[e] = U2F(PADD(ua, ub));
            float2 dd = U2F(PSUB(ua, ub));
            r[e + 1] = make_float2(dd.x * wc.x - dd.y * wc.y,
                                   dd.x * wc.y + dd.y * wc.x);
        }
        // transpose (padded, conflict-free)
#pragma unroll
        for (int e = 0; e < 32; e++) tbuf[33 * lt + e] = r[e];
        __syncwarp();
#pragma unroll
        for (int p = 0; p < 32; p++) r[p] = tbuf[33 * p + lt];
        __syncwarp();

        // stage D (L=32, radix-4): constant twiddles W_32; p0=0 identity
        {
            const float2 WD1[8] = {{1.f,0.f},{0.98078528f,-0.19509032f},{0.92387953f,-0.38268343f},{0.83146961f,-0.55557023f},{0.70710678f,-0.70710678f},{0.55557023f,-0.83146961f},{0.38268343f,-0.92387953f},{0.19509032f,-0.98078528f}};
            const float2 WD2[8] = {{1.f,0.f},{0.92387953f,-0.38268343f},{0.70710678f,-0.70710678f},{0.38268343f,-0.92387953f},{0.f,-1.f},{-0.38268343f,-0.92387953f},{-0.70710678f,-0.70710678f},{-0.92387953f,-0.38268343f}};
            const float2 WD3[8] = {{1.f,0.f},{0.83146961f,-0.55557023f},{0.38268343f,-0.92387953f},{-0.19509032f,-0.98078528f},{-0.70710678f,-0.70710678f},{-0.98078528f,-0.19509032f},{-0.92387953f,0.38268343f},{-0.55557023f,0.83146961f}};
            BFLY4P0(r[0], r[8], r[16], r[24]);
#pragma unroll
            for (int p0 = 1; p0 < 8; p0++)
                BFLY4P(r[p0], r[p0 + 8], r[p0 + 16], r[p0 + 24], WD1[p0], WD2[p0], WD3[p0]);
        }
        // stage E (L=8, radix-4): q=0 identity, q=1 constant
        {
            const float2 WE1 = {0.70710678f, -0.70710678f};
            const float2 WE2 = {0.f, -1.f};
            const float2 WE3 = {-0.70710678f, -0.70710678f};
#pragma unroll
            for (int pb = 0; pb < 32; pb += 8) {
                BFLY4P0(r[pb + 0], r[pb + 2], r[pb + 4], r[pb + 6]);
                BFLY4P(r[pb + 1], r[pb + 3], r[pb + 5], r[pb + 7], WE1, WE2, WE3);
            }
        }
        // stage F (L=2) + magnitudes + fused reductions
        float rS = 0.0f, rST = 0.0f;
#pragma unroll
        for (int h = 0; h < 16; h++) {
            u64 ua = F2U(r[2 * h]), ub = F2U(r[2 * h + 1]);
            float2 y0 = U2F(PADD(ua, ub));
            float2 y1 = U2F(PSUB(ua, ub));
            float s0 = y0.x * y0.x + y0.y * y0.y;
            float s1 = y1.x * y1.x + y1.y * y1.y;
            lmax = fmaxf(lmax, fmaxf(s0, s1));
            rS += s0 + s1;
            rST += s0 * tv[HCOL(2 * h)] + s1 * tv[HCOL(2 * h + 1)];
        }
        float rT = 0.0f, rT2 = 0.0f;
#pragma unroll
        for (int m = 0; m < 32; m++) { rT += tv[m]; rT2 += tv[m] * tv[m]; }

        dS += rS; dST += rST; dT += rT; dT2a += rT2;
    }

    // block reduction
    double vS = dS, vST = dST, vT = dT, vT2 = dT2a; float vM = lmax;
#pragma unroll
    for (int o = 16; o > 0; o >>= 1) {
        vS  += __shfl_down_sync(0xffffffffu, vS,  o);
        vST += __shfl_down_sync(0xffffffffu, vST, o);
        vT  += __shfl_down_sync(0xffffffffu, vT,  o);
        vT2 += __shfl_down_sync(0xffffffffu, vT2, o);
        vM   = fmaxf(vM, __shfl_down_sync(0xffffffffu, vM, o));
    }
    __shared__ double sS[8], sST[8], sT[8], sT2[8];
    __shared__ float  sM[8];
    if (lt == 0) { sS[wid] = vS; sST[wid] = vST; sT[wid] = vT; sT2[wid] = vT2; sM[wid] = vM; }
    __syncthreads();
    if (tid == 0) {
        double aS = 0, aST = 0, aT = 0, aT2 = 0; float aM = 0.0f;
#pragma unroll
        for (int i = 0; i < 8; i++) {
            aS += sS[i]; aST += sST[i]; aT += sT[i]; aT2 += sT2[i];
            aM = fmaxf(aM, sM[i]);
        }
        atomicAdd(&g_accS[b],  aS);
        atomicAdd(&g_accST[b], aST);
        atomicAdd(&g_accT[b],  aT);
        atomicAdd(&g_accT2[b], aT2);
        atomicMax(&g_accMax[b], __float_as_uint(aM));
    }
}

// ---------------- kernel 3: frog + final mean ----------------
__global__ void finalize_kernel(float* out) {
    int b = threadIdx.x;   // 32 threads
    double M    = (double)__uint_as_float(g_accMax[b]);
    double sum1 = g_accST[b] / M;
    double mu   = sum1 / g_accT2[b];
    double diff = g_accS[b] / M - mu * g_accT[b];
    double r2   = diff * diff;
    float frog  = (r2 == 0.0) ? 0.0f : (float)(sqrt(r2) / (double)NN);
    float v = g_mse[b] + frog;
#pragma unroll
    for (int o = 16; o > 0; o >>= 1) v += __shfl_down_sync(0xffffffffu, v, o);
    if (b == 0) out[0] = v * (1.0f / BB);
}

// ---------------- launch ----------------
extern "C" void kernel_launch(void* const* d_in, const int* in_sizes, int n_in,
                              void* d_out, int out_size) {
    const float* pred  = (const float*)d_in[0];
    const float* label = (const float*)d_in[1];
    const float* shg   = (const float*)d_in[2];
    float* out = (float*)d_out;

    const int SHG_SMEM = (2 * NN + NN + 3 * 256 + 3 * 64 + 8 * TPAD) * sizeof(float2);
    static int attr_done = 0;
    if (!attr_done) {
        cudaFuncSetAttribute(shg_kernel, cudaFuncAttributeMaxDynamicSharedMemorySize, SHG_SMEM);
        attr_done = 1;
    }

    hilbert_kernel<<<BB, NT>>>(pred);
    shg_kernel<<<dim3(33, BB), NT, SHG_SMEM>>>(shg, label);
    finalize_kernel<<<1, 32>>>(out);
}

// round 14
// speedup vs baseline: 1.1544x; 1.1323x over previous
#include <cuda_runtime.h>
#include <math.h>

#define NN 1024
#define NT 256
#define BB 32

typedef unsigned long long u64;

// ---------------- device scratch ----------------
__device__ float2   g_pa[BB * NN];
__device__ float2   g_pam[BB * NN];
__device__ float2   g_tw[1024];           // W_1024^k, full table
__device__ double   g_accS[BB], g_accST[BB], g_accT[BB], g_accT2[BB];
__device__ unsigned g_accMax[BB];
__device__ float    g_mse[BB];

__device__ __forceinline__ float2 cmulf(float2 a, float2 b) {
    return make_float2(a.x * b.x - a.y * b.y, a.x * b.y + a.y * b.x);
}

// twiddle: W_1024^i computed in fp32 trig (angle via one double multiply)
__device__ __forceinline__ float2 twval(int i) {
    float ang = (float)(-6.283185307179586 / 1024.0 * (double)i);
    float s, c;
    sincosf(ang, &s, &c);
    return make_float2(c, s);
}

// ---------------- packed helpers (one complex value per u64) ----------------
__device__ __forceinline__ u64 F2U(float2 v) {
    u64 r; asm("mov.b64 %0,{%1,%2};" : "=l"(r) : "f"(v.x), "f"(v.y)); return r;
}
__device__ __forceinline__ float2 U2F(u64 v) {
    float2 r; asm("mov.b64 {%0,%1},%2;" : "=f"(r.x), "=f"(r.y) : "l"(v)); return r;
}
__device__ __forceinline__ u64 PADD(u64 a, u64 b) {
    u64 r; asm("add.rn.f32x2 %0,%1,%2;" : "=l"(r) : "l"(a), "l"(b)); return r;
}
__device__ __forceinline__ u64 PSUB(u64 a, u64 b) {
    const u64 n1 = 0xBF800000BF800000ULL;
    u64 r; asm("fma.rn.f32x2 %0,%1,%2,%3;" : "=l"(r) : "l"(b), "l"(n1), "l"(a)); return r;
}

// radix-4 DIF butterfly: packed adds, scalar cross-terms + cmuls
#define BFLY4P(A, Bq, C, D, W1, W2, W3) do {                                  \
    u64 ua = F2U(A), ub = F2U(Bq), uc = F2U(C), ud = F2U(D);                  \
    u64 t0 = PADD(ua, uc), t1 = PSUB(ua, uc);                                 \
    u64 t2 = PADD(ub, ud), t3 = PSUB(ub, ud);                                 \
    A = U2F(PADD(t0, t2));                                                    \
    float2 ci = U2F(PSUB(t0, t2));                                            \
    float2 f1 = U2F(t1), f3 = U2F(t3);                                        \
    float bx = f1.x + f3.y, by = f1.y - f3.x;                                 \
    float dx = f1.x - f3.y, dy = f1.y + f3.x;                                 \
    Bq = make_float2(bx * W1.x - by * W1.y, bx * W1.y + by * W1.x);           \
    C  = make_float2(ci.x * W2.x - ci.y * W2.y, ci.x * W2.y + ci.y * W2.x);   \
    D  = make_float2(dx * W3.x - dy * W3.y, dx * W3.y + dy * W3.x);           \
} while (0)

// identity-twiddle butterfly (W1=W2=W3=1): pure adds
#define BFLY4P0(A, Bq, C, D) do {                                             \
    u64 ua = F2U(A), ub = F2U(Bq), uc = F2U(C), ud = F2U(D);                  \
    u64 t0 = PADD(ua, uc), t1 = PSUB(ua, uc);                                 \
    u64 t2 = PADD(ub, ud), t3 = PSUB(ub, ud);                                 \
    A = U2F(PADD(t0, t2));                                                    \
    C = U2F(PSUB(t0, t2));                                                    \
    float2 f1 = U2F(t1), f3 = U2F(t3);                                        \
    Bq = make_float2(f1.x + f3.y, f1.y - f3.x);                               \
    D  = make_float2(f1.x - f3.y, f1.y + f3.x);                               \
} while (0)

// bin->tref-column mapping (col = k ^ 512), as tv[] index: compile-time per p
#define HCOL(p) (((((p) >> 3) & 3)) | ((((p) >> 1) & 3) << 2) | (((((p) & 1)) ^ 1) << 4))

// ---------------- radix-2 smem FFT (hilbert only) ----------------
template <bool INV>
__device__ __forceinline__ void fft1024(float2* sm, const float2* tw, int tid) {
#pragma unroll
    for (int e = 0; e < 4; e++) {
        int i = tid + e * NT;
        int j = __brev(i) >> 22;
        if (i < j) { float2 t = sm[i]; sm[i] = sm[j]; sm[j] = t; }
    }
    __syncthreads();
#pragma unroll
    for (int s = 1; s <= 10; s++) {
        int half = 1 << (s - 1);
#pragma unroll
        for (int e = 0; e < 2; e++) {
            int m   = tid + e * NT;
            int pos = m & (half - 1);
            int i0  = ((m >> (s - 1)) << s) + pos;
            int i1  = i0 + half;
            float2 w = tw[pos << (10 - s)];
            float wy = INV ? -w.y : w.y;
            float2 q = sm[i1];
            float2 v = make_float2(q.x * w.x - q.y * wy, q.x * wy + q.y * w.x);
            float2 u = sm[i0];
            sm[i0] = make_float2(u.x + v.x, u.y + v.y);
            sm[i1] = make_float2(u.x - v.x, u.y - v.y);
        }
        __syncthreads();
    }
    if (INV) {
        const float sc = 1.0f / (float)NN;
#pragma unroll
        for (int e = 0; e < 4; e++) { int i = tid + e * NT; sm[i].x *= sc; sm[i].y *= sc; }
        __syncthreads();
    }
}

// ---------------- kernel 1: hilbert + modulation + (block 0: init globals) ----------------
__global__ void hilbert_kernel(const float* __restrict__ pred) {
    __shared__ float2 sm[NN];
    __shared__ float2 tw[NN / 2];
    int b = blockIdx.x, tid = threadIdx.x;

    // per-block twiddles (fp32 trig — cheap)
#pragma unroll
    for (int e = 0; e < 2; e++) {
        int i = tid + e * NT;
        tw[i] = twval(i);
    }
    // block 0 additionally publishes the full table + zeroed accumulators for shg
    if (b == 0) {
#pragma unroll
        for (int e = 0; e < 4; e++) {
            int i = tid + e * NT;
            g_tw[i] = twval(i);
        }
        if (tid < BB) {
            g_accS[tid] = 0.0; g_accST[tid] = 0.0; g_accT[tid] = 0.0; g_accT2[tid] = 0.0;
            g_accMax[tid] = 0u;
        }
    }
#pragma unroll
    for (int e = 0; e < 4; e++) {
        int i = tid + e * NT;
        sm[i] = make_float2(pred[b * NN + i], 0.0f);
    }
    __syncthreads();
    fft1024<false>(sm, tw, tid);
#pragma unroll
    for (int e = 0; e < 4; e++) {
        int i = tid + e * NT;
        float h = (i < NN / 2) ? 0.0f : ((i == NN / 2) ? 1.0f : 2.0f);
        sm[i].x *= h; sm[i].y *= h;
    }
    __syncthreads();
    fft1024<true>(sm, tw, tid);
#pragma unroll
    for (int e = 0; e < 4; e++) {
        int i = tid + e * NT;
        float2 a = sm[i];
        g_pa[b * NN + i] = a;
        float ang = (float)(2.0 * 1175000000000000.0 * 1.5e-15 * (double)(i - 512));
        float cs, sn;
        sincosf(ang, &sn, &cs);
        g_pam[b * NN + i] = cmulf(a, make_float2(cs, -sn));
    }
}

// ---------------- mse body (runs inside the fused shg launch) ----------------
__device__ void mse_body(const float* __restrict__ label, int b, int tid) {
    const float* lr = label + (size_t)b * 2 * NN;
    const float* li = lr + NN;

    __shared__ int s_frR, s_laR, s_frI, s_laI;
    if (tid == 0) { s_frR = NN; s_laR = -1; s_frI = NN; s_laI = -1; }
    __syncthreads();
    int frR = NN, laR = -1, frI = NN, laI = -1;
    for (int t = tid; t < NN; t += NT) {
        if (fabsf(lr[t]) > 0.01f) { frR = min(frR, t); laR = max(laR, t); }
        if (fabsf(li[t]) > 0.01f) { frI = min(frI, t); laI = max(laI, t); }
    }
    atomicMin(&s_frR, frR); atomicMax(&s_laR, laR);
    atomicMin(&s_frI, frI); atomicMax(&s_laI, laI);
    __syncthreads();
    int fr_r = (s_frR == NN) ? 0 : s_frR;
    int la_r = (s_laR < 0) ? (NN - 1) : s_laR;
    int fr_i = (s_frI == NN) ? 0 : s_frI;
    int la_i = (s_laI < 0) ? (NN - 1) : s_laI;
    int first = min(fr_r, fr_i);
    int last  = max(la_r, la_i);

    float sR = 0, sI = 0, sInt = 0, sPh = 0;
    for (int t = tid; t < NN; t += NT) {
        float2 p = g_pa[b * NN + t];
        float LR = lr[t], LI = li[t];
        bool inr = (t >= first) && (t < last);
        float pm = inr ? 10.0f : 1.0f;
        float dr = p.x - LR, di = p.y - LI;
        float pint = p.x * p.x + p.y * p.y;
        float lint = LR * LR + LI * LI;
        float dint = pint - lint;
        sR   += dr * dr * pm;
        sI   += di * di * pm;
        sInt += dint * dint * pm;
        if (inr) {
            float dp = atan2f(p.y, p.x) - atan2f(LI, LR);
            sPh += dp * dp;
        }
    }
    float tot = sR + sI + sInt + sPh;
#pragma unroll
    for (int o = 16; o > 0; o >>= 1) tot += __shfl_down_sync(0xffffffffu, tot, o);
    __shared__ float rA[8];
    int w = tid >> 5, lane = tid & 31;
    if (lane == 0) rA[w] = tot;
    __syncthreads();
    if (tid == 0) {
        float a = 0;
#pragma unroll
        for (int i = 0; i < 8; i++) a += rA[i];
        g_mse[b] = a * (1.0f / NN) * 0.25f;
    }
}

// ---------------- kernel 2: fused SHG + MSE ----------------
// grid (33, BB): blockIdx.x < 32 -> SHG rows; blockIdx.x == 32 -> MSE for batch b.
#define TPAD 1056   // 33*32 float2 per warp

__global__ __launch_bounds__(256, 2) void shg_kernel(const float* __restrict__ tref,
                                                     const float* __restrict__ label) {
    extern __shared__ char sraw[];
    int tid = threadIdx.x;
    int b = blockIdx.y;

    if (blockIdx.x == 32) { mse_body(label, b, tid); return; }

    float2* paS2    = (float2*)sraw;        // 2048 (16KB, duplicated)
    float2* pamS    = paS2 + 2 * NN;        // 1024 (8KB)
    float2* twA1    = pamS + NN;            // 256
    float2* twA2    = twA1 + 256;           // 256
    float2* twA3    = twA2 + 256;           // 256
    float2* twB1    = twA3 + 256;           // 64
    float2* twB2    = twB1 + 64;            // 64
    float2* twB3    = twB2 + 64;            // 64
    float2* tbufAll = twB3 + 64;            // 8 * 1056 (66KB)

    int wid = tid >> 5, lt = tid & 31;
    float2* tbuf = tbufAll + wid * TPAD;

    for (int i = tid; i < NN; i += NT) {
        float2 v = g_pa[b * NN + i];
        paS2[i] = v; paS2[i + NN] = v;
        pamS[i] = g_pam[b * NN + i];
    }
    if (tid < 256) {
        twA1[tid] = g_tw[tid];
        twA2[tid] = g_tw[2 * tid];
        twA3[tid] = g_tw[3 * tid];
    }
    if (tid < 64) {
        twB1[tid] = g_tw[4 * tid];
        twB2[tid] = g_tw[8 * tid];
        twB3[tid] = g_tw[12 * tid];
    }
    __syncthreads();

    const float* base = tref + (size_t)b * NN * NN;
    const int kb = ((lt >> 3) & 3) | (((lt >> 1) & 3) << 2) | ((lt & 1) << 4);
    const float2 wc = g_tw[16 * lt];   // stage-C twiddle, loop-invariant

    float lmax = 0.0f;
    double dS = 0.0, dST = 0.0, dT = 0.0, dT2a = 0.0;

    for (int rr = 0; rr < 4; rr++) {
        int d = blockIdx.x * 32 + wid * 4 + rr;   // 0..1023
        int delay = d - 512;
        int tb = (lt - delay) & (NN - 1);

        // tref loads issued first: each instruction's 32 lanes hit one 128B line
        const float* rowp = base + (size_t)d * NN + kb;
        float tv[32];
#pragma unroll
        for (int m = 0; m < 32; m++) tv[m] = rowp[32 * m];

        // input build, layout: r[e] = c[lt + 32e]
        float2 r[32];
#pragma unroll
        for (int e = 0; e < 32; e++)
            r[e] = cmulf(pamS[lt + 32 * e], paS2[tb + 32 * e]);

        // stage A (L=1024, radix-4): q = lt+32e0; stride-1 table lookups
#pragma unroll
        for (int e0 = 0; e0 < 8; e0++) {
            int q = lt + 32 * e0;
            float2 w1 = twA1[q], w2 = twA2[q], w3 = twA3[q];
            BFLY4P(r[e0], r[e0 + 8], r[e0 + 16], r[e0 + 24], w1, w2, w3);
        }
        // stage B (L=256, radix-4): i = lt+32e1 (q = 4i); stride-1 lookups
#pragma unroll
        for (int e1 = 0; e1 < 2; e1++) {
            int i = lt + 32 * e1;
            float2 w1 = twB1[i], w2 = twB2[i], w3 = twB3[i];
#pragma unroll
            for (int blk = 0; blk < 4; blk++) {
                int q0 = 8 * blk + e1;
                BFLY4P(r[q0], r[q0 + 2], r[q0 + 4], r[q0 + 6], w1, w2, w3);
            }
        }
        // stage C (L=64, radix-2): hoisted register twiddle
#pragma unroll
        for (int e = 0; e < 32; e += 2) {
            u64 ua = F2U(r[e]), ub = F2U(r[e + 1]);
            r[e] = U2F(PADD(ua, ub));
            float2 dd = U2F(PSUB(ua, ub));
            r[e + 1] = make_float2(dd.x * wc.x - dd.y * wc.y,
                                   dd.x * wc.y + dd.y * wc.x);
        }
        // transpose (padded, conflict-free)
#pragma unroll
        for (int e = 0; e < 32; e++) tbuf[33 * lt + e] = r[e];
        __syncwarp();
#pragma unroll
        for (int p = 0; p < 32; p++) r[p] = tbuf[33 * p + lt];
        __syncwarp();

        // stage D (L=32, radix-4): constant twiddles W_32; p0=0 identity
        {
            const float2 WD1[8] = {{1.f,0.f},{0.98078528f,-0.19509032f},{0.92387953f,-0.38268343f},{0.83146961f,-0.55557023f},{0.70710678f,-0.70710678f},{0.55557023f,-0.83146961f},{0.38268343f,-0.92387953f},{0.19509032f,-0.98078528f}};
            const float2 WD2[8] = {{1.f,0.f},{0.92387953f,-0.38268343f},{0.70710678f,-0.70710678f},{0.38268343f,-0.92387953f},{0.f,-1.f},{-0.38268343f,-0.92387953f},{-0.70710678f,-0.70710678f},{-0.92387953f,-0.38268343f}};
            const float2 WD3[8] = {{1.f,0.f},{0.83146961f,-0.55557023f},{0.38268343f,-0.92387953f},{-0.19509032f,-0.98078528f},{-0.70710678f,-0.70710678f},{-0.98078528f,-0.19509032f},{-0.92387953f,0.38268343f},{-0.55557023f,0.83146961f}};
            BFLY4P0(r[0], r[8], r[16], r[24]);
#pragma unroll
            for (int p0 = 1; p0 < 8; p0++)
                BFLY4P(r[p0], r[p0 + 8], r[p0 + 16], r[p0 + 24], WD1[p0], WD2[p0], WD3[p0]);
        }
        // stage E (L=8, radix-4): q=0 identity, q=1 constant
        {
            const float2 WE1 = {0.70710678f, -0.70710678f};
            const float2 WE2 = {0.f, -1.f};
            const float2 WE3 = {-0.70710678f, -0.70710678f};
#pragma unroll
            for (int pb = 0; pb < 32; pb += 8) {
                BFLY4P0(r[pb + 0], r[pb + 2], r[pb + 4], r[pb + 6]);
                BFLY4P(r[pb + 1], r[pb + 3], r[pb + 5], r[pb + 7], WE1, WE2, WE3);
            }
        }
        // stage F (L=2) + magnitudes + fused reductions
        float rS = 0.0f, rST = 0.0f;
#pragma unroll
        for (int h = 0; h < 16; h++) {
            u64 ua = F2U(r[2 * h]), ub = F2U(r[2 * h + 1]);
            float2 y0 = U2F(PADD(ua, ub));
            float2 y1 = U2F(PSUB(ua, ub));
            float s0 = y0.x * y0.x + y0.y * y0.y;
            float s1 = y1.x * y1.x + y1.y * y1.y;
            lmax = fmaxf(lmax, fmaxf(s0, s1));
            rS += s0 + s1;
            rST += s0 * tv[HCOL(2 * h)] + s1 * tv[HCOL(2 * h + 1)];
        }
        float rT = 0.0f, rT2 = 0.0f;
#pragma unroll
        for (int m = 0; m < 32; m++) { rT += tv[m]; rT2 += tv[m] * tv[m]; }

        dS += rS; dST += rST; dT += rT; dT2a += rT2;
    }

    // block reduction
    double vS = dS, vST = dST, vT = dT, vT2 = dT2a; float vM = lmax;
#pragma unroll
    for (int o = 16; o > 0; o >>= 1) {
        vS  += __shfl_down_sync(0xffffffffu, vS,  o);
        vST += __shfl_down_sync(0xffffffffu, vST, o);
        vT  += __shfl_down_sync(0xffffffffu, vT,  o);
        vT2 += __shfl_down_sync(0xffffffffu, vT2, o);
        vM   = fmaxf(vM, __shfl_down_sync(0xffffffffu, vM, o));
    }
    __shared__ double sS[8], sST[8], sT[8], sT2[8];
    __shared__ float  sM[8];
    if (lt == 0) { sS[wid] = vS; sST[wid] = vST; sT[wid] = vT; sT2[wid] = vT2; sM[wid] = vM; }
    __syncthreads();
    if (tid == 0) {
        double aS = 0, aST = 0, aT = 0, aT2 = 0; float aM = 0.0f;
#pragma unroll
        for (int i = 0; i < 8; i++) {
            aS += sS[i]; aST += sST[i]; aT += sT[i]; aT2 += sT2[i];
            aM = fmaxf(aM, sM[i]);
        }
        atomicAdd(&g_accS[b],  aS);
        atomicAdd(&g_accST[b], aST);
        atomicAdd(&g_accT[b],  aT);
        atomicAdd(&g_accT2[b], aT2);
        atomicMax(&g_accMax[b], __float_as_uint(aM));
    }
}

// ---------------- kernel 3: frog + final mean ----------------
__global__ void finalize_kernel(float* out) {
    int b = threadIdx.x;   // 32 threads
    double M    = (double)__uint_as_float(g_accMax[b]);
    double sum1 = g_accST[b] / M;
    double mu   = sum1 / g_accT2[b];
    double diff = g_accS[b] / M - mu * g_accT[b];
    double r2   = diff * diff;
    float frog  = (r2 == 0.0) ? 0.0f : (float)(sqrt(r2) / (double)NN);
    float v = g_mse[b] + frog;
#pragma unroll
    for (int o = 16; o > 0; o >>= 1) v += __shfl_down_sync(0xffffffffu, v, o);
    if (b == 0) out[0] = v * (1.0f / BB);
}

// ---------------- launch ----------------
extern "C" void kernel_launch(void* const* d_in, const int* in_sizes, int n_in,
                              void* d_out, int out_size) {
    const float* pred  = (const float*)d_in[0];
    const float* label = (const float*)d_in[1];
    const float* shg   = (const float*)d_in[2];
    float* out = (float*)d_out;

    const int SHG_SMEM = (2 * NN + NN + 3 * 256 + 3 * 64 + 8 * TPAD) * sizeof(float2);
    static int attr_done = 0;
    if (!attr_done) {
        cudaFuncSetAttribute(shg_kernel, cudaFuncAttributeMaxDynamicSharedMemorySize, SHG_SMEM);
        attr_done = 1;
    }

    hilbert_kernel<<<BB, NT>>>(pred);
    shg_kernel<<<dim3(33, BB), NT, SHG_SMEM>>>(shg, label);
    finalize_kernel<<<1, 32>>>(out);
}

// round 15
// speedup vs baseline: 1.1804x; 1.0226x over previous
#include <cuda_runtime.h>
#include <math.h>

#define NN 1024
#define NT 256
#define BB 32

typedef unsigned long long u64;

// ---------------- device scratch ----------------
__device__ float2   g_pa[BB * NN];
__device__ float2   g_pam[BB * NN];
__device__ float2   g_tw[1024];           // W_1024^k, full table
__device__ double   g_accS[BB], g_accST[BB], g_accT[BB], g_accT2[BB];
__device__ unsigned g_accMax[BB];
__device__ float    g_mse[BB];
__device__ unsigned g_flag[BB];           // per-batch hilbert-done flags
__device__ unsigned g_done;               // completion counter (shg+mse blocks)

__device__ __forceinline__ float2 cmulf(float2 a, float2 b) {
    return make_float2(a.x * b.x - a.y * b.y, a.x * b.y + a.y * b.x);
}

// twiddle: W_1024^i computed in fp32 trig
__device__ __forceinline__ float2 twval(int i) {
    float ang = (float)(-6.283185307179586 / 1024.0 * (double)i);
    float s, c;
    sincosf(ang, &s, &c);
    return make_float2(c, s);
}

// ---------------- packed helpers ----------------
__device__ __forceinline__ u64 F2U(float2 v) {
    u64 r; asm("mov.b64 %0,{%1,%2};" : "=l"(r) : "f"(v.x), "f"(v.y)); return r;
}
__device__ __forceinline__ float2 U2F(u64 v) {
    float2 r; asm("mov.b64 {%0,%1},%2;" : "=f"(r.x), "=f"(r.y) : "l"(v)); return r;
}
__device__ __forceinline__ u64 PADD(u64 a, u64 b) {
    u64 r; asm("add.rn.f32x2 %0,%1,%2;" : "=l"(r) : "l"(a), "l"(b)); return r;
}
__device__ __forceinline__ u64 PSUB(u64 a, u64 b) {
    const u64 n1 = 0xBF800000BF800000ULL;
    u64 r; asm("fma.rn.f32x2 %0,%1,%2,%3;" : "=l"(r) : "l"(b), "l"(n1), "l"(a)); return r;
}

#define BFLY4P(A, Bq, C, D, W1, W2, W3) do {                                  \
    u64 ua = F2U(A), ub = F2U(Bq), uc = F2U(C), ud = F2U(D);                  \
    u64 t0 = PADD(ua, uc), t1 = PSUB(ua, uc);                                 \
    u64 t2 = PADD(ub, ud), t3 = PSUB(ub, ud);                                 \
    A = U2F(PADD(t0, t2));                                                    \
    float2 ci = U2F(PSUB(t0, t2));                                            \
    float2 f1 = U2F(t1), f3 = U2F(t3);                                        \
    float bx = f1.x + f3.y, by = f1.y - f3.x;                                 \
    float dx = f1.x - f3.y, dy = f1.y + f3.x;                                 \
    Bq = make_float2(bx * W1.x - by * W1.y, bx * W1.y + by * W1.x);           \
    C  = make_float2(ci.x * W2.x - ci.y * W2.y, ci.x * W2.y + ci.y * W2.x);   \
    D  = make_float2(dx * W3.x - dy * W3.y, dx * W3.y + dy * W3.x);           \
} while (0)

#define BFLY4P0(A, Bq, C, D) do {                                             \
    u64 ua = F2U(A), ub = F2U(Bq), uc = F2U(C), ud = F2U(D);                  \
    u64 t0 = PADD(ua, uc), t1 = PSUB(ua, uc);                                 \
    u64 t2 = PADD(ub, ud), t3 = PSUB(ub, ud);                                 \
    A = U2F(PADD(t0, t2));                                                    \
    C = U2F(PSUB(t0, t2));                                                    \
    float2 f1 = U2F(t1), f3 = U2F(t3);                                        \
    Bq = make_float2(f1.x + f3.y, f1.y - f3.x);                               \
    D  = make_float2(f1.x - f3.y, f1.y + f3.x);                               \
} while (0)

#define HCOL(p) (((((p) >> 3) & 3)) | ((((p) >> 1) & 3) << 2) | (((((p) & 1)) ^ 1) << 4))

// ---------------- radix-2 smem FFT (hilbert role) ----------------
template <bool INV>
__device__ __forceinline__ void fft1024(float2* sm, const float2* tw, int tid) {
#pragma unroll
    for (int e = 0; e < 4; e++) {
        int i = tid + e * NT;
        int j = __brev(i) >> 22;
        if (i < j) { float2 t = sm[i]; sm[i] = sm[j]; sm[j] = t; }
    }
    __syncthreads();
#pragma unroll
    for (int s = 1; s <= 10; s++) {
        int half = 1 << (s - 1);
#pragma unroll
        for (int e = 0; e < 2; e++) {
            int m   = tid + e * NT;
            int pos = m & (half - 1);
            int i0  = ((m >> (s - 1)) << s) + pos;
            int i1  = i0 + half;
            float2 w = tw[pos << (10 - s)];
            float wy = INV ? -w.y : w.y;
            float2 q = sm[i1];
            float2 v = make_float2(q.x * w.x - q.y * wy, q.x * wy + q.y * w.x);
            float2 u = sm[i0];
            sm[i0] = make_float2(u.x + v.x, u.y + v.y);
            sm[i1] = make_float2(u.x - v.x, u.y - v.y);
        }
        __syncthreads();
    }
    if (INV) {
        const float sc = 1.0f / (float)NN;
#pragma unroll
        for (int e = 0; e < 4; e++) { int i = tid + e * NT; sm[i].x *= sc; sm[i].y *= sc; }
        __syncthreads();
    }
}

// ---------------- kernel 1: reset flags/counters/accumulators ----------------
__global__ void reset_kernel() {
    int t = threadIdx.x;   // 64 threads
    if (t < BB) {
        g_accS[t] = 0.0; g_accST[t] = 0.0; g_accT[t] = 0.0; g_accT2[t] = 0.0;
        g_accMax[t] = 0u; g_flag[t] = 0u;
    }
    if (t == 32) g_done = 0u;
}

// ---------------- role bodies ----------------
__device__ void hilbert_body(const float* __restrict__ pred, int b, int tid, char* sraw) {
    float2* sm = (float2*)sraw;
    float2* tw = sm + NN;
#pragma unroll
    for (int e = 0; e < 2; e++) { int i = tid + e * NT; tw[i] = twval(i); }
    if (b == 0) {
#pragma unroll
        for (int e = 0; e < 4; e++) { int i = tid + e * NT; g_tw[i] = twval(i); }
    }
#pragma unroll
    for (int e = 0; e < 4; e++) {
        int i = tid + e * NT;
        sm[i] = make_float2(pred[b * NN + i], 0.0f);
    }
    __syncthreads();
    fft1024<false>(sm, tw, tid);
#pragma unroll
    for (int e = 0; e < 4; e++) {
        int i = tid + e * NT;
        float h = (i < NN / 2) ? 0.0f : ((i == NN / 2) ? 1.0f : 2.0f);
        sm[i].x *= h; sm[i].y *= h;
    }
    __syncthreads();
    fft1024<true>(sm, tw, tid);
#pragma unroll
    for (int e = 0; e < 4; e++) {
        int i = tid + e * NT;
        float2 a = sm[i];
        g_pa[b * NN + i] = a;
        float ang = (float)(2.0 * 1175000000000000.0 * 1.5e-15 * (double)(i - 512));
        float cs, sn;
        sincosf(ang, &sn, &cs);
        g_pam[b * NN + i] = cmulf(a, make_float2(cs, -sn));
    }
    __threadfence();
    __syncthreads();
    if (tid == 0) atomicExch(&g_flag[b], 1u);
}

__device__ void wait_flag(int b, int tid) {
    if (tid == 0) {
        while (atomicAdd(&g_flag[b], 0u) == 0u) { }
        if (b != 0) while (atomicAdd(&g_flag[0], 0u) == 0u) { }
    }
    __syncthreads();
    __threadfence();
}

__device__ void mse_body(const float* __restrict__ label, int b, int tid) {
    const float* lr = label + (size_t)b * 2 * NN;
    const float* li = lr + NN;

    __shared__ int s_frR, s_laR, s_frI, s_laI;
    if (tid == 0) { s_frR = NN; s_laR = -1; s_frI = NN; s_laI = -1; }
    __syncthreads();
    int frR = NN, laR = -1, frI = NN, laI = -1;
    for (int t = tid; t < NN; t += NT) {
        if (fabsf(lr[t]) > 0.01f) { frR = min(frR, t); laR = max(laR, t); }
        if (fabsf(li[t]) > 0.01f) { frI = min(frI, t); laI = max(laI, t); }
    }
    atomicMin(&s_frR, frR); atomicMax(&s_laR, laR);
    atomicMin(&s_frI, frI); atomicMax(&s_laI, laI);
    __syncthreads();
    int fr_r = (s_frR == NN) ? 0 : s_frR;
    int la_r = (s_laR < 0) ? (NN - 1) : s_laR;
    int fr_i = (s_frI == NN) ? 0 : s_frI;
    int la_i = (s_laI < 0) ? (NN - 1) : s_laI;
    int first = min(fr_r, fr_i);
    int last  = max(la_r, la_i);

    float sR = 0, sI = 0, sInt = 0, sPh = 0;
    for (int t = tid; t < NN; t += NT) {
        float2 p = g_pa[b * NN + t];
        float LR = lr[t], LI = li[t];
        bool inr = (t >= first) && (t < last);
        float pm = inr ? 10.0f : 1.0f;
        float dr = p.x - LR, di = p.y - LI;
        float pint = p.x * p.x + p.y * p.y;
        float lint = LR * LR + LI * LI;
        float dint = pint - lint;
        sR   += dr * dr * pm;
        sI   += di * di * pm;
        sInt += dint * dint * pm;
        if (inr) {
            float dp = atan2f(p.y, p.x) - atan2f(LI, LR);
            sPh += dp * dp;
        }
    }
    float tot = sR + sI + sInt + sPh;
#pragma unroll
    for (int o = 16; o > 0; o >>= 1) tot += __shfl_down_sync(0xffffffffu, tot, o);
    __shared__ float rA[8];
    int w = tid >> 5, lane = tid & 31;
    if (lane == 0) rA[w] = tot;
    __syncthreads();
    if (tid == 0) {
        float a = 0;
#pragma unroll
        for (int i = 0; i < 8; i++) a += rA[i];
        g_mse[b] = a * (1.0f / NN) * 0.25f;
    }
}

#define TPAD 1056   // 33*32 float2 per warp

__device__ void shg_body(const float* __restrict__ tref, int b, int xi, int tid, char* sraw) {
    float2* paS2    = (float2*)sraw;        // 2048
    float2* pamS    = paS2 + 2 * NN;        // 1024
    float2* twA1    = pamS + NN;            // 256
    float2* twA2    = twA1 + 256;           // 256
    float2* twA3    = twA2 + 256;           // 256
    float2* twB1    = twA3 + 256;           // 64
    float2* twB2    = twB1 + 64;            // 64
    float2* twB3    = twB2 + 64;            // 64
    float2* tbufAll = twB3 + 64;            // 8 * 1056

    int wid = tid >> 5, lt = tid & 31;
    float2* tbuf = tbufAll + wid * TPAD;

    for (int i = tid; i < NN; i += NT) {
        float2 v = g_pa[b * NN + i];
        paS2[i] = v; paS2[i + NN] = v;
        pamS[i] = g_pam[b * NN + i];
    }
    if (tid < 256) {
        twA1[tid] = g_tw[tid];
        twA2[tid] = g_tw[2 * tid];
        twA3[tid] = g_tw[3 * tid];
    }
    if (tid < 64) {
        twB1[tid] = g_tw[4 * tid];
        twB2[tid] = g_tw[8 * tid];
        twB3[tid] = g_tw[12 * tid];
    }
    __syncthreads();

    const float* base = tref + (size_t)b * NN * NN;
    const int kb = ((lt >> 3) & 3) | (((lt >> 1) & 3) << 2) | ((lt & 1) << 4);
    const float2 wc = g_tw[16 * lt];

    float lmax = 0.0f;
    double dS = 0.0, dST = 0.0, dT = 0.0, dT2a = 0.0;

    for (int rr = 0; rr < 4; rr++) {
        int d = xi * 32 + wid * 4 + rr;   // 0..1023
        int delay = d - 512;
        int tb = (lt - delay) & (NN - 1);

        const float* rowp = base + (size_t)d * NN + kb;
        float tv[32];
#pragma unroll
        for (int m = 0; m < 32; m++) tv[m] = rowp[32 * m];

        float2 r[32];
#pragma unroll
        for (int e = 0; e < 32; e++)
            r[e] = cmulf(pamS[lt + 32 * e], paS2[tb + 32 * e]);

        // stage A (L=1024)
#pragma unroll
        for (int e0 = 0; e0 < 8; e0++) {
            int q = lt + 32 * e0;
            float2 w1 = twA1[q], w2 = twA2[q], w3 = twA3[q];
            BFLY4P(r[e0], r[e0 + 8], r[e0 + 16], r[e0 + 24], w1, w2, w3);
        }
        // stage B (L=256)
#pragma unroll
        for (int e1 = 0; e1 < 2; e1++) {
            int i = lt + 32 * e1;
            float2 w1 = twB1[i], w2 = twB2[i], w3 = twB3[i];
#pragma unroll
            for (int blk = 0; blk < 4; blk++) {
                int q0 = 8 * blk + e1;
                BFLY4P(r[q0], r[q0 + 2], r[q0 + 4], r[q0 + 6], w1, w2, w3);
            }
        }
        // stage C (L=64)
#pragma unroll
        for (int e = 0; e < 32; e += 2) {
            u64 ua = F2U(r[e]), ub = F2U(r[e + 1]);
            r[e] = U2F(PADD(ua, ub));
            float2 dd = U2F(PSUB(ua, ub));
            r[e + 1] = make_float2(dd.x * wc.x - dd.y * wc.y,
                                   dd.x * wc.y + dd.y * wc.x);
        }
        // transpose
#pragma unroll
        for (int e = 0; e < 32; e++) tbuf[33 * lt + e] = r[e];
        __syncwarp();
#pragma unroll
        for (int p = 0; p < 32; p++) r[p] = tbuf[33 * p + lt];
        __syncwarp();

        // stage D (L=32)
        {
            const float2 WD1[8] = {{1.f,0.f},{0.98078528f,-0.19509032f},{0.92387953f,-0.38268343f},{0.83146961f,-0.55557023f},{0.70710678f,-0.70710678f},{0.55557023f,-0.83146961f},{0.38268343f,-0.92387953f},{0.19509032f,-0.98078528f}};
            const float2 WD2[8] = {{1.f,0.f},{0.92387953f,-0.38268343f},{0.70710678f,-0.70710678f},{0.38268343f,-0.92387953f},{0.f,-1.f},{-0.38268343f,-0.92387953f},{-0.70710678f,-0.70710678f},{-0.92387953f,-0.38268343f}};
            const float2 WD3[8] = {{1.f,0.f},{0.83146961f,-0.55557023f},{0.38268343f,-0.92387953f},{-0.19509032f,-0.98078528f},{-0.70710678f,-0.70710678f},{-0.98078528f,-0.19509032f},{-0.92387953f,0.38268343f},{-0.55557023f,0.83146961f}};
            BFLY4P0(r[0], r[8], r[16], r[24]);
#pragma unroll
            for (int p0 = 1; p0 < 8; p0++)
                BFLY4P(r[p0], r[p0 + 8], r[p0 + 16], r[p0 + 24], WD1[p0], WD2[p0], WD3[p0]);
        }
        // stage E (L=8)
        {
            const float2 WE1 = {0.70710678f, -0.70710678f};
            const float2 WE2 = {0.f, -1.f};
            const float2 WE3 = {-0.70710678f, -0.70710678f};
#pragma unroll
            for (int pb = 0; pb < 32; pb += 8) {
                BFLY4P0(r[pb + 0], r[pb + 2], r[pb + 4], r[pb + 6]);
                BFLY4P(r[pb + 1], r[pb + 3], r[pb + 5], r[pb + 7], WE1, WE2, WE3);
            }
        }
        // stage F (L=2) + magnitudes + fused reductions
        float rS = 0.0f, rST = 0.0f;
#pragma unroll
        for (int h = 0; h < 16; h++) {
            u64 ua = F2U(r[2 * h]), ub = F2U(r[2 * h + 1]);
            float2 y0 = U2F(PADD(ua, ub));
            float2 y1 = U2F(PSUB(ua, ub));
            float s0 = y0.x * y0.x + y0.y * y0.y;
            float s1 = y1.x * y1.x + y1.y * y1.y;
            lmax = fmaxf(lmax, fmaxf(s0, s1));
            rS += s0 + s1;
            rST += s0 * tv[HCOL(2 * h)] + s1 * tv[HCOL(2 * h + 1)];
        }
        float rT = 0.0f, rT2 = 0.0f;
#pragma unroll
        for (int m = 0; m < 32; m++) { rT += tv[m]; rT2 += tv[m] * tv[m]; }

        dS += rS; dST += rST; dT += rT; dT2a += rT2;
    }

    // block reduction
    double vS = dS, vST = dST, vT = dT, vT2 = dT2a; float vM = lmax;
#pragma unroll
    for (int o = 16; o > 0; o >>= 1) {
        vS  += __shfl_down_sync(0xffffffffu, vS,  o);
        vST += __shfl_down_sync(0xffffffffu, vST, o);
        vT  += __shfl_down_sync(0xffffffffu, vT,  o);
        vT2 += __shfl_down_sync(0xffffffffu, vT2, o);
        vM   = fmaxf(vM, __shfl_down_sync(0xffffffffu, vM, o));
    }
    __shared__ double sS[8], sST[8], sT[8], sT2[8];
    __shared__ float  sM[8];
    if (lt == 0) { sS[wid] = vS; sST[wid] = vST; sT[wid] = vT; sT2[wid] = vT2; sM[wid] = vM; }
    __syncthreads();
    if (tid == 0) {
        double aS = 0, aST = 0, aT = 0, aT2 = 0; float aM = 0.0f;
#pragma unroll
        for (int i = 0; i < 8; i++) {
            aS += sS[i]; aST += sST[i]; aT += sT[i]; aT2 += sT2[i];
            aM = fmaxf(aM, sM[i]);
        }
        atomicAdd(&g_accS[b],  aS);
        atomicAdd(&g_accST[b], aST);
        atomicAdd(&g_accT[b],  aT);
        atomicAdd(&g_accT2[b], aT2);
        atomicMax(&g_accMax[b], __float_as_uint(aM));
    }
}

// ---------------- kernel 2: mega (hilbert + shg + mse + finalize) ----------------
// 1-D grid of 1088 blocks; bids 0..31 hilbert, 32..1055 shg, 1056..1087 mse.
// Wave 1 (296 resident blocks) contains all hilbert blocks -> no deadlock.
__global__ __launch_bounds__(256, 2) void mega_kernel(const float* __restrict__ tref,
                                                      const float* __restrict__ label,
                                                      const float* __restrict__ pred,
                                                      float* __restrict__ out) {
    extern __shared__ char sraw[];
    int bid = blockIdx.x, tid = threadIdx.x;

    if (bid < 32) {
        hilbert_body(pred, bid, tid, sraw);
        return;
    }
    if (bid < 1056) {
        int idx = bid - 32;
        int b = idx >> 5, xi = idx & 31;
        wait_flag(b, tid);
        shg_body(tref, b, xi, tid, sraw);
    } else {
        int b = bid - 1056;
        wait_flag(b, tid);
        mse_body(label, b, tid);
    }

    // completion epilogue: last of the 1056 accumulating blocks runs finalize
    __shared__ unsigned s_done;
    __syncthreads();
    if (tid == 0) {
        __threadfence();
        s_done = atomicAdd(&g_done, 1u) + 1u;
    }
    __syncthreads();
    if (s_done == 1056u) {
        __threadfence();
        if (tid < 32) {
            int b = tid;
            double M    = (double)__uint_as_float(g_accMax[b]);
            double sum1 = g_accST[b] / M;
            double mu   = sum1 / g_accT2[b];
            double diff = g_accS[b] / M - mu * g_accT[b];
            double r2   = diff * diff;
            float frog  = (r2 == 0.0) ? 0.0f : (float)(sqrt(r2) / (double)NN);
            float v = g_mse[b] + frog;
#pragma unroll
            for (int o = 16; o > 0; o >>= 1) v += __shfl_down_sync(0xffffffffu, v, o);
            if (b == 0) out[0] = v * (1.0f / BB);
        }
    }
}

// ---------------- launch ----------------
extern "C" void kernel_launch(void* const* d_in, const int* in_sizes, int n_in,
                              void* d_out, int out_size) {
    const float* pred  = (const float*)d_in[0];
    const float* label = (const float*)d_in[1];
    const float* shg   = (const float*)d_in[2];
    float* out = (float*)d_out;

    const int SHG_SMEM = (2 * NN + NN + 3 * 256 + 3 * 64 + 8 * TPAD) * sizeof(float2);
    static int attr_done = 0;
    if (!attr_done) {
        cudaFuncSetAttribute(mega_kernel, cudaFuncAttributeMaxDynamicSharedMemorySize, SHG_SMEM);
        attr_done = 1;
    }

    reset_kernel<<<1, 64>>>();
    mega_kernel<<<1088, NT, SHG_SMEM>>>(shg, label, pred, out);
}